// round 10
// baseline (speedup 1.0000x reference)
#include <cuda_runtime.h>
#include <cuda_bf16.h>
#include <cstdint>

// ---------------- problem-size constants (fixed by this problem) -------------
#define MAXN   100000
#define NREL   8
#define INF    128
#define HID    32
#define NCOLS  (NREL*HID)      // 256
#define NGMAX  64
#define EPB    1024            // edges per block in scatter2

// ---------------- device scratch (static: no allocations allowed) ------------
// Self-reset for graph replay: zero at module load; every consumer kernel
// resets what it consumed so the next replay sees zeros again.
__device__ __align__(128) float g_y1[(size_t)MAXN * NCOLS];   // x @ [W1_0..W1_7]
__device__ __align__(128) float g_h1[(size_t)MAXN * HID];     // scatter1 accum (reset by k_relu)
__device__ __align__(128) float g_h1b[(size_t)MAXN * HID];    // relu output
__device__ __align__(128) float g_rso[NREL * MAXN];           // rsqrt(max(deg_out,1))
__device__ __align__(128) float g_rsi[NREL * MAXN];           // rsqrt(max(deg_in,1))
__device__ __align__(128) int   g_dego[NREL * MAXN];          // reset by k_prep
__device__ __align__(128) int   g_degi[NREL * MAXN];          // reset by k_prep
__device__ __align__(128) int   g_cnt[NGMAX];                 // reset by k_relu
__device__ __align__(128) float g_inv[NGMAX];                 // 1/max(cnt,1)
__device__ __align__(128) float g_V[NREL * HID * 2];          // W2_r @ Wc
// bf16 hi/lo weight image, [n][k] layout (k contiguous, 256B/row):
// [0,64K) = B_hi (256 n-rows x 128 k), [64K,128K) = B_lo
__device__ __align__(128) unsigned char g_wimg[131072];

__device__ __forceinline__ uint32_t smem_u32(const void* p) {
    uint32_t a;
    asm("{ .reg .u64 t; cvta.to.shared.u64 t, %1; cvt.u32.u64 %0, t; }" : "=r"(a) : "l"(p));
    return a;
}
__device__ __forceinline__ void cp16(uint32_t daddr, const void* src) {
    asm volatile("cp.async.cg.shared.global [%0], [%1], 16;" :: "r"(daddr), "l"(src));
}
__device__ __forceinline__ void ldsm4(uint32_t* r, uint32_t addr) {
    asm volatile("ldmatrix.sync.aligned.m8n8.x4.shared.b16 {%0,%1,%2,%3}, [%4];"
        : "=r"(r[0]), "=r"(r[1]), "=r"(r[2]), "=r"(r[3]) : "r"(addr));
}

// ---------------- K2: wconv (blocks 0-63) + degrees + graph counts ------------
__global__ void k_deg(const int* __restrict__ src, const int* __restrict__ dst,
                      const int* __restrict__ gids, const float* __restrict__ W1,
                      int n_nodes, int n_edges) {
    if (blockIdx.x < 64) {
        // W1 -> bf16 hi/lo image, [n][k] layout
        int i = blockIdx.x * blockDim.x + threadIdx.x;   // 0..16383
        int n = i >> 6, k = (i & 63) * 2;
        int r = n >> 5, f = n & 31;
        float w0 = W1[r * (INF * HID) + k * HID + f];
        float w1 = W1[r * (INF * HID) + (k + 1) * HID + f];
        __nv_bfloat16 h0 = __float2bfloat16(w0);
        __nv_bfloat16 h1 = __float2bfloat16(w1);
        __nv_bfloat16 l0 = __float2bfloat16(w0 - __bfloat162float(h0));
        __nv_bfloat16 l1 = __float2bfloat16(w1 - __bfloat162float(h1));
        uint32_t off = (uint32_t)n * 256u + (uint32_t)k * 2u;
        __nv_bfloat162 hv; hv.x = h0; hv.y = h1;
        __nv_bfloat162 lv; lv.x = l0; lv.y = l1;
        *(__nv_bfloat162*)(g_wimg + off) = hv;
        *(__nv_bfloat162*)(g_wimg + 65536 + off) = lv;
        return;
    }
    int i = (blockIdx.x - 64) * blockDim.x + threadIdx.x;
    int te = NREL * n_edges;
    if (i < te) {
        int r = i / n_edges;
        atomicAdd(&g_dego[r * n_nodes + src[i]], 1);
        atomicAdd(&g_degi[r * n_nodes + dst[i]], 1);
    } else if (i < te + n_nodes) {
        atomicAdd(&g_cnt[gids[i - te]], 1);
    }
}

// ---------------- K3: rsqrt tables, V_r = W2_r @ Wc, out init; deg reset ------
__global__ void k_prep(const float* __restrict__ W2, const float* __restrict__ Wc,
                       const float* __restrict__ b2, const float* __restrict__ bc,
                       float* __restrict__ out, int n_nodes, int n_graphs) {
    int i = blockIdx.x * blockDim.x + threadIdx.x;
    int t1 = NREL * n_nodes;
    if (i < t1) {
        g_rso[i] = rsqrtf((float)max(g_dego[i], 1));
        g_rsi[i] = rsqrtf((float)max(g_degi[i], 1));
        g_dego[i] = 0;                 // self-reset for next graph replay
        g_degi[i] = 0;
    } else if (i < t1 + NREL * HID * 2) {
        int v = i - t1;
        int r = v >> 6, f = (v >> 1) & 31, o = v & 1;
        float s = 0.f;
        #pragma unroll
        for (int j = 0; j < HID; j++) s += W2[r * (HID * HID) + f * HID + j] * Wc[j * 2 + o];
        g_V[v] = s;
    } else if (i < t1 + NREL * HID * 2 + 2 * n_graphs) {
        int u = i - t1 - NREL * HID * 2;
        int g = u >> 1, o = u & 1;
        if (o == 0) g_inv[g] = 1.f / (float)max(g_cnt[g], 1);
        float s = 0.f;
        for (int j = 0; j < HID; j++) {
            float bs = 0.f;
            #pragma unroll
            for (int r = 0; r < NREL; r++) bs += b2[r * HID + j];
            s += bs * Wc[j * 2 + o];
        }
        out[u] = bc[o] + (g_cnt[g] > 0 ? s : 0.f);   // empty graph -> pooled = 0
    }
}

// ---------------- K4: HMMA GEMM  y1 = x @ [W1_0..W1_7] ------------------------
// CTA: 128 nodes x 256 cols x FULL K=128 in smem (204KB, 1 CTA/SM). 512 thr,
// 16 warps (4M x 4N), warp tile 32x64. bf16 hi/lo split. ldmatrix.x4 loads.
// MMAs are PASS-GROUPED: per 4-ni block issue all hi*hi (8 indep accs), then
// all lo*hi, then all hi*lo -> RAW reuse distance 8 (vs 1 before).
#define SROW  272
#define SA_H  0
#define SA_L  (128 * SROW)               // 34816
#define SB_H  (2 * 128 * SROW)           // 69632
#define SB_L  (SB_H + 256 * SROW)        // 139264
#define SMEM_G (SB_L + 256 * SROW)       // 208896

__device__ __forceinline__ void mma16816(float* c, const uint32_t* a, const uint32_t* b) {
    asm volatile("mma.sync.aligned.m16n8k16.row.col.f32.bf16.bf16.f32 "
        "{%0,%1,%2,%3}, {%4,%5,%6,%7}, {%8,%9}, {%0,%1,%2,%3};"
        : "+f"(c[0]), "+f"(c[1]), "+f"(c[2]), "+f"(c[3])
        : "r"(a[0]), "r"(a[1]), "r"(a[2]), "r"(a[3]), "r"(b[0]), "r"(b[1]));
}

__global__ __launch_bounds__(512, 1) void k_gemm_mma(const float* __restrict__ x,
                                                     int n_nodes) {
    extern __shared__ unsigned char smem[];
    uint32_t sb = smem_u32(smem);
    int t = threadIdx.x, wid = t >> 5, lid = t & 31;
    int gid = lid >> 2, tid4 = lid & 3;
    int node0 = blockIdx.x * 128;

    // ---- B: bulk cp.async of the pre-converted hi/lo image (async w.r.t. A) --
    {
        const unsigned char* bh = g_wimg;
        #pragma unroll
        for (int p = 0; p < 8; p++) {
            int idx = p * 512 + t;               // 0..4095
            int n = idx >> 4, c = idx & 15;
            uint32_t so = (uint32_t)n * 256u + (uint32_t)c * 16u;
            cp16(sb + SB_H + n * SROW + c * 16, bh + so);
            cp16(sb + SB_L + n * SROW + c * 16, bh + 65536 + so);
        }
        asm volatile("cp.async.commit_group;" ::: "memory");
    }
    // ---- A: load x, convert to bf16 hi/lo, store (overlaps B cp.async) -------
    #pragma unroll
    for (int p = 0; p < 8; p++) {
        int idx = p * 512 + t;                   // 0..4095
        int m = idx >> 5, k = (idx & 31) * 4;
        int gn = node0 + m;
        float4 v = make_float4(0.f, 0.f, 0.f, 0.f);
        if (gn < n_nodes) v = *(const float4*)(x + (size_t)gn * INF + k);
        __nv_bfloat16 h0 = __float2bfloat16(v.x), h1 = __float2bfloat16(v.y);
        __nv_bfloat16 h2 = __float2bfloat16(v.z), h3 = __float2bfloat16(v.w);
        __nv_bfloat16 l0 = __float2bfloat16(v.x - __bfloat162float(h0));
        __nv_bfloat16 l1 = __float2bfloat16(v.y - __bfloat162float(h1));
        __nv_bfloat16 l2 = __float2bfloat16(v.z - __bfloat162float(h2));
        __nv_bfloat16 l3 = __float2bfloat16(v.w - __bfloat162float(h3));
        __nv_bfloat162 a, b;
        a.x = h0; a.y = h1; b.x = h2; b.y = h3;
        uint2 hp; hp.x = *(uint32_t*)&a; hp.y = *(uint32_t*)&b;
        a.x = l0; a.y = l1; b.x = l2; b.y = l3;
        uint2 lp; lp.x = *(uint32_t*)&a; lp.y = *(uint32_t*)&b;
        *(uint2*)(smem + SA_H + m * SROW + k * 2) = hp;
        *(uint2*)(smem + SA_L + m * SROW + k * 2) = lp;
    }
    asm volatile("cp.async.wait_group 0;" ::: "memory");
    __syncthreads();

    int mrow0 = (wid & 3) * 32;          // 4 M-groups
    int ncol0 = (wid >> 2) * 64;         // 4 N-groups
    float acc[2][8][4];
    #pragma unroll
    for (int mi = 0; mi < 2; mi++)
        #pragma unroll
        for (int ni = 0; ni < 8; ni++)
            #pragma unroll
            for (int q = 0; q < 4; q++) acc[mi][ni][q] = 0.f;

    // ldmatrix per-lane addresses.
    // A (m16k16, matrices {m0-7,k0},{m8-15,k0},{m0-7,+16B},{m8-15,+16B}):
    int l3 = lid & 7, grp = lid >> 3;
    uint32_t a_row = mrow0 + l3 + (grp & 1) * 8;
    uint32_t a_koff = (grp >> 1) * 16;
    uint32_t aH0 = sb + SA_H + a_row * SROW + a_koff;
    uint32_t aH1 = aH0 + 16 * SROW;
    uint32_t aL0 = aH0 + (SA_L - SA_H);
    uint32_t aL1 = aH1 + (SA_L - SA_H);
    // B pair (ni, ni+1): matrices {n0-7,k0},{n0-7,+16B},{n8-15,k0},{n8-15,+16B}
    //   -> r0,r1 = b(ni), r2,r3 = b(ni+1)
    uint32_t b_row = ncol0 + l3 + (grp >> 1) * 8;
    uint32_t b_koff = (grp & 1) * 16;
    uint32_t bH = sb + SB_H + b_row * SROW + b_koff;
    uint32_t bL = bH + (SB_L - SB_H);

    #pragma unroll
    for (int ks = 0; ks < 8; ks++) {
        uint32_t kb = ks * 32;
        uint32_t ah[2][4], al[2][4];
        ldsm4(ah[0], aH0 + kb);
        ldsm4(ah[1], aH1 + kb);
        ldsm4(al[0], aL0 + kb);
        ldsm4(al[1], aL1 + kb);
        #pragma unroll
        for (int p = 0; p < 2; p++) {        // ni group: 4p .. 4p+3
            // B frags for 4 ni: bh4[q] covers ni pair (4p+2q, 4p+2q+1)
            uint32_t bh4[2][4], bl4[2][4];
            ldsm4(bh4[0], bH + (2 * p) * 16 * SROW + kb);
            ldsm4(bh4[1], bH + (2 * p + 1) * 16 * SROW + kb);
            ldsm4(bl4[0], bL + (2 * p) * 16 * SROW + kb);
            ldsm4(bl4[1], bL + (2 * p + 1) * 16 * SROW + kb);
            // pass 0: hi*hi (8 independent accumulators)
            #pragma unroll
            for (int j = 0; j < 4; j++) {
                int ni = 4 * p + j;
                const uint32_t* bb = &bh4[j >> 1][2 * (j & 1)];
                mma16816(acc[0][ni], ah[0], bb);
                mma16816(acc[1][ni], ah[1], bb);
            }
            // pass 1: lo*hi
            #pragma unroll
            for (int j = 0; j < 4; j++) {
                int ni = 4 * p + j;
                const uint32_t* bb = &bh4[j >> 1][2 * (j & 1)];
                mma16816(acc[0][ni], al[0], bb);
                mma16816(acc[1][ni], al[1], bb);
            }
            // pass 2: hi*lo
            #pragma unroll
            for (int j = 0; j < 4; j++) {
                int ni = 4 * p + j;
                const uint32_t* bb = &bl4[j >> 1][2 * (j & 1)];
                mma16816(acc[0][ni], ah[0], bb);
                mma16816(acc[1][ni], ah[1], bb);
            }
        }
    }

    // ---- epilogue: write y1 ----------------------------------------------------
    #pragma unroll
    for (int mi = 0; mi < 2; mi++) {
        int r0 = node0 + mrow0 + mi * 16 + gid;
        #pragma unroll
        for (int ni = 0; ni < 8; ni++) {
            int col = ncol0 + ni * 8 + tid4 * 2;
            if (r0 < n_nodes)
                *(float2*)(g_y1 + (size_t)r0 * NCOLS + col) =
                    make_float2(acc[mi][ni][0], acc[mi][ni][1]);
            if (r0 + 8 < n_nodes)
                *(float2*)(g_y1 + (size_t)(r0 + 8) * NCOLS + col) =
                    make_float2(acc[mi][ni][2], acc[mi][ni][3]);
        }
    }
}

// ---------------- K5: layer-1 edge scatter (both deg scales folded) ----------
__global__ void k_scatter1(const int* __restrict__ src, const int* __restrict__ dst,
                           int n_nodes, int n_edges) {
    int i = blockIdx.x * blockDim.x + threadIdx.x;
    int tot = NREL * n_edges * 8;
    if (i >= tot) return;
    int e = i >> 3, q = i & 7;
    int r = e / n_edges;
    int s = src[e], d = dst[e];
    float sc = g_rso[r * n_nodes + s] * g_rsi[r * n_nodes + d];
    float4 v = *(const float4*)(g_y1 + (size_t)s * NCOLS + r * HID + q * 4);
    v.x *= sc; v.y *= sc; v.z *= sc; v.w *= sc;
    atomicAdd((float4*)(g_h1 + (size_t)d * HID + q * 4), v);
}

// ---------------- K6: bias + relu (h1 -> h1b); resets h1 and cnt --------------
__global__ void k_relu(const float* __restrict__ b1, int n_nodes) {
    __shared__ float bs[HID];
    if (threadIdx.x < HID) {
        float s = 0.f;
        #pragma unroll
        for (int r = 0; r < NREL; r++) s += b1[r * HID + threadIdx.x];
        bs[threadIdx.x] = s;
    }
    __syncthreads();
    int i = blockIdx.x * blockDim.x + threadIdx.x;
    if (i < n_nodes * HID) {
        g_h1b[i] = fmaxf(g_h1[i] + bs[i & 31], 0.f);
        g_h1[i] = 0.f;                  // self-reset for next graph replay
    }
    if (blockIdx.x == 0 && threadIdx.x < NGMAX) g_cnt[threadIdx.x] = 0;
}

// -------- K7: fused layer-2 + mean-pool + classifier (edge -> out[64,2]) -----
__global__ __launch_bounds__(256) void k_scatter2(const int* __restrict__ src,
                                                  const int* __restrict__ dst,
                                                  const int* __restrict__ gids,
                                                  float* __restrict__ out,
                                                  int n_nodes, int n_edges) {
    __shared__ float zs[NGMAX * 2];
    __shared__ float Vs[NREL * HID * 2];
    __shared__ float inv_s[NGMAX];
    int t = threadIdx.x;
    if (t < NGMAX * 2) zs[t] = 0.f;
    for (int i = t; i < NREL * HID * 2; i += 256) Vs[i] = g_V[i];
    if (t < NGMAX) inv_s[t] = g_inv[t];
    __syncthreads();

    int te = NREL * n_edges;
    int e0 = blockIdx.x * EPB;
    #pragma unroll
    for (int it = 0; it < EPB / 256; it++) {
        int e = e0 + it * 256 + t;
        if (e < te) {
            int r = e / n_edges;
            int s = src[e], d = dst[e];
            int g = gids[d];
            float coeff = g_rso[r * n_nodes + s] * g_rsi[r * n_nodes + d] * inv_s[g];
            const float4* hp = (const float4*)(g_h1b + (size_t)s * HID);
            const float* vp = Vs + r * (HID * 2);
            float a0 = 0.f, a1 = 0.f;
            #pragma unroll
            for (int q = 0; q < 8; q++) {
                float4 hv = hp[q];
                a0 += hv.x * vp[q * 8 + 0] + hv.y * vp[q * 8 + 2] +
                      hv.z * vp[q * 8 + 4] + hv.w * vp[q * 8 + 6];
                a1 += hv.x * vp[q * 8 + 1] + hv.y * vp[q * 8 + 3] +
                      hv.z * vp[q * 8 + 5] + hv.w * vp[q * 8 + 7];
            }
            atomicAdd(&zs[g * 2 + 0], a0 * coeff);
            atomicAdd(&zs[g * 2 + 1], a1 * coeff);
        }
    }
    __syncthreads();
    if (t < NGMAX * 2) atomicAdd(&out[t], zs[t]);
}

// ---------------- launch ------------------------------------------------------
extern "C" void kernel_launch(void* const* d_in, const int* in_sizes, int n_in,
                              void* d_out, int out_size) {
    int off = (n_in >= 11) ? 1 : 0;
    const float* x   = (const float*)d_in[0];
    const int*   src = (const int*)d_in[1];
    const int*   dst = (const int*)d_in[2];
    const int*   gid = (const int*)d_in[3];
    const float* W1  = (const float*)d_in[4 + off];
    const float* b1  = (const float*)d_in[5 + off];
    const float* W2  = (const float*)d_in[6 + off];
    const float* b2  = (const float*)d_in[7 + off];
    const float* Wc  = (const float*)d_in[8 + off];
    const float* bc  = (const float*)d_in[9 + off];
    float* out = (float*)d_out;

    int n_nodes  = in_sizes[3];
    int n_edges  = in_sizes[1] / NREL;
    int n_graphs = out_size / 2;

    cudaFuncSetAttribute(k_gemm_mma, cudaFuncAttributeMaxDynamicSharedMemorySize,
                         SMEM_G);

    int tot1 = NREL * n_edges + n_nodes;
    k_deg<<<64 + (tot1 + 255) / 256, 256>>>(src, dst, gid, W1, n_nodes, n_edges);

    int tot2 = NREL * n_nodes + NREL * HID * 2 + 2 * n_graphs;
    k_prep<<<(tot2 + 255) / 256, 256>>>(W2, Wc, b2, bc, out, n_nodes, n_graphs);

    k_gemm_mma<<<(n_nodes + 127) / 128, 512, SMEM_G>>>(x, n_nodes);

    int tot5 = NREL * n_edges * 8;
    k_scatter1<<<(tot5 + 255) / 256, 256>>>(src, dst, n_nodes, n_edges);

    int tot6 = HID * n_nodes;
    k_relu<<<(tot6 + 255) / 256, 256>>>(b1, n_nodes);

    k_scatter2<<<(NREL * n_edges + EPB - 1) / EPB, 256>>>(src, dst, gid, out,
                                                          n_nodes, n_edges);
}

// round 11
// speedup vs baseline: 1.0535x; 1.0535x over previous
#include <cuda_runtime.h>
#include <cuda_bf16.h>
#include <cstdint>

// ---------------- problem-size constants (fixed by this problem) -------------
#define MAXN   100000
#define NREL   8
#define INF    128
#define HID    32
#define NCOLS  (NREL*HID)      // 256
#define NGMAX  64
#define EPB    1024            // edges per block in scatter2

// ---------------- device scratch (static: no allocations allowed) ------------
// Replay-safety: h1 is zeroed by k_prep at the START of every replay (before
// scatter1 accumulates); deg arrays self-reset in k_prep; g_cnt resets in
// k_scatter1 block 0 (after k_prep consumed it).
__device__ __align__(128) float g_y1[(size_t)MAXN * NCOLS];   // x @ [W1_0..W1_7]
__device__ __align__(128) float g_h1[(size_t)MAXN * HID];     // scatter1 accum
__device__ __align__(128) float g_rso[NREL * MAXN];           // rsqrt(max(deg_out,1))
__device__ __align__(128) float g_rsi[NREL * MAXN];           // rsqrt(max(deg_in,1))
__device__ __align__(128) int   g_dego[NREL * MAXN];          // reset by k_prep
__device__ __align__(128) int   g_degi[NREL * MAXN];          // reset by k_prep
__device__ __align__(128) int   g_cnt[NGMAX];                 // reset by k_scatter1
__device__ __align__(128) float g_inv[NGMAX];                 // 1/max(cnt,1)
__device__ __align__(128) float g_V[NREL * HID * 2];          // W2_r @ Wc
// bf16 hi/lo weight image, [n][k] layout (k contiguous, 256B/row):
// [0,64K) = B_hi (256 n-rows x 128 k), [64K,128K) = B_lo
__device__ __align__(128) unsigned char g_wimg[131072];

__device__ __forceinline__ uint32_t smem_u32(const void* p) {
    uint32_t a;
    asm("{ .reg .u64 t; cvta.to.shared.u64 t, %1; cvt.u32.u64 %0, t; }" : "=r"(a) : "l"(p));
    return a;
}
__device__ __forceinline__ void cp16(uint32_t daddr, const void* src) {
    asm volatile("cp.async.cg.shared.global [%0], [%1], 16;" :: "r"(daddr), "l"(src));
}
__device__ __forceinline__ void ldsm4(uint32_t* r, uint32_t addr) {
    asm volatile("ldmatrix.sync.aligned.m8n8.x4.shared.b16 {%0,%1,%2,%3}, [%4];"
        : "=r"(r[0]), "=r"(r[1]), "=r"(r[2]), "=r"(r[3]) : "r"(addr));
}

// ---------------- K2: wconv (blocks 0-63) + degrees + graph counts ------------
__global__ void k_deg(const int* __restrict__ src, const int* __restrict__ dst,
                      const int* __restrict__ gids, const float* __restrict__ W1,
                      int n_nodes, int n_edges) {
    if (blockIdx.x < 64) {
        // W1 -> bf16 hi/lo image, [n][k] layout
        int i = blockIdx.x * blockDim.x + threadIdx.x;   // 0..16383
        int n = i >> 6, k = (i & 63) * 2;
        int r = n >> 5, f = n & 31;
        float w0 = W1[r * (INF * HID) + k * HID + f];
        float w1 = W1[r * (INF * HID) + (k + 1) * HID + f];
        __nv_bfloat16 h0 = __float2bfloat16(w0);
        __nv_bfloat16 h1 = __float2bfloat16(w1);
        __nv_bfloat16 l0 = __float2bfloat16(w0 - __bfloat162float(h0));
        __nv_bfloat16 l1 = __float2bfloat16(w1 - __bfloat162float(h1));
        uint32_t off = (uint32_t)n * 256u + (uint32_t)k * 2u;
        __nv_bfloat162 hv; hv.x = h0; hv.y = h1;
        __nv_bfloat162 lv; lv.x = l0; lv.y = l1;
        *(__nv_bfloat162*)(g_wimg + off) = hv;
        *(__nv_bfloat162*)(g_wimg + 65536 + off) = lv;
        return;
    }
    int i = (blockIdx.x - 64) * blockDim.x + threadIdx.x;
    int te = NREL * n_edges;
    if (i < te) {
        int r = i / n_edges;
        atomicAdd(&g_dego[r * n_nodes + src[i]], 1);
        atomicAdd(&g_degi[r * n_nodes + dst[i]], 1);
    } else if (i < te + n_nodes) {
        atomicAdd(&g_cnt[gids[i - te]], 1);
    }
}

// ------ K3: rsqrt tables, V, out init, deg reset, h1 zero (replay start) -----
__global__ void k_prep(const float* __restrict__ W2, const float* __restrict__ Wc,
                       const float* __restrict__ b2, const float* __restrict__ bc,
                       float* __restrict__ out, int n_nodes, int n_graphs) {
    int i = blockIdx.x * blockDim.x + threadIdx.x;
    int t1 = NREL * n_nodes;
    int t2 = t1 + NREL * HID * 2;
    int t3 = t2 + 2 * n_graphs;
    if (i < t1) {
        g_rso[i] = rsqrtf((float)max(g_dego[i], 1));
        g_rsi[i] = rsqrtf((float)max(g_degi[i], 1));
        g_dego[i] = 0;                 // self-reset for next graph replay
        g_degi[i] = 0;
    } else if (i < t2) {
        int v = i - t1;
        int r = v >> 6, f = (v >> 1) & 31, o = v & 1;
        float s = 0.f;
        #pragma unroll
        for (int j = 0; j < HID; j++) s += W2[r * (HID * HID) + f * HID + j] * Wc[j * 2 + o];
        g_V[v] = s;
    } else if (i < t3) {
        int u = i - t2;
        int g = u >> 1, o = u & 1;
        if (o == 0) g_inv[g] = 1.f / (float)max(g_cnt[g], 1);
        float s = 0.f;
        for (int j = 0; j < HID; j++) {
            float bs = 0.f;
            #pragma unroll
            for (int r = 0; r < NREL; r++) bs += b2[r * HID + j];
            s += bs * Wc[j * 2 + o];
        }
        out[u] = bc[o] + (g_cnt[g] > 0 ? s : 0.f);   // empty graph -> pooled = 0
    } else if (i < t3 + (n_nodes * HID) / 4) {
        // zero h1 (float4) before scatter1 accumulates this replay
        ((float4*)g_h1)[i - t3] = make_float4(0.f, 0.f, 0.f, 0.f);
    }
}

// ---------------- K4: HMMA GEMM  y1 = x @ [W1_0..W1_7] ------------------------
// CTA: 64 nodes x 128 cols x full K=128. smem 104.4KB -> 2 CTAs/SM so one CTA's
// staging overlaps the other's mainloop (R8-R10 showed mainloop is at its HMMA
// floor; the exposed time was staging/epilogue with 1 CTA/SM).
// 256 threads, 8 warps (2M x 4N), warp tile 32x32, acc 32 regs/thread.
// bf16 hi/lo split (3 passes), ldmatrix.x4 fragment loads.
#define SROW  272
#define SA_H  0
#define SA_L  (64 * SROW)                // 17408
#define SB_H  (2 * 64 * SROW)            // 34816
#define SB_L  (SB_H + 128 * SROW)        // 69632
#define SMEM_G (SB_L + 128 * SROW)       // 104448

__device__ __forceinline__ void mma16816(float* c, const uint32_t* a, const uint32_t* b) {
    asm volatile("mma.sync.aligned.m16n8k16.row.col.f32.bf16.bf16.f32 "
        "{%0,%1,%2,%3}, {%4,%5,%6,%7}, {%8,%9}, {%0,%1,%2,%3};"
        : "+f"(c[0]), "+f"(c[1]), "+f"(c[2]), "+f"(c[3])
        : "r"(a[0]), "r"(a[1]), "r"(a[2]), "r"(a[3]), "r"(b[0]), "r"(b[1]));
}

__global__ __launch_bounds__(256, 2) void k_gemm_mma(const float* __restrict__ x,
                                                     int n_nodes) {
    extern __shared__ unsigned char smem[];
    uint32_t sb = smem_u32(smem);
    int t = threadIdx.x, wid = t >> 5, lid = t & 31;
    int gid = lid >> 2, tid4 = lid & 3;
    int node0 = blockIdx.x * 64;
    int cbase = blockIdx.y * 128;

    // ---- B: cp.async of this CTA's 128-col half of the hi/lo image -----------
    {
        const unsigned char* bh = g_wimg;
        #pragma unroll
        for (int p = 0; p < 8; p++) {
            int idx = p * 256 + t;               // 0..2047
            int n = idx >> 4, c = idx & 15;      // n 0..127, c 0..15
            uint32_t so = (uint32_t)(cbase + n) * 256u + (uint32_t)c * 16u;
            cp16(sb + SB_H + n * SROW + c * 16, bh + so);
            cp16(sb + SB_L + n * SROW + c * 16, bh + 65536 + so);
        }
        asm volatile("cp.async.commit_group;" ::: "memory");
    }
    // ---- A: load x, convert to bf16 hi/lo, store (overlaps B cp.async) -------
    #pragma unroll
    for (int p = 0; p < 8; p++) {
        int idx = p * 256 + t;                   // 0..2047
        int m = idx >> 5, k = (idx & 31) * 4;    // m 0..63
        int gn = node0 + m;
        float4 v = make_float4(0.f, 0.f, 0.f, 0.f);
        if (gn < n_nodes) v = *(const float4*)(x + (size_t)gn * INF + k);
        __nv_bfloat16 h0 = __float2bfloat16(v.x), h1 = __float2bfloat16(v.y);
        __nv_bfloat16 h2 = __float2bfloat16(v.z), h3 = __float2bfloat16(v.w);
        __nv_bfloat16 l0 = __float2bfloat16(v.x - __bfloat162float(h0));
        __nv_bfloat16 l1 = __float2bfloat16(v.y - __bfloat162float(h1));
        __nv_bfloat16 l2 = __float2bfloat16(v.z - __bfloat162float(h2));
        __nv_bfloat16 l3 = __float2bfloat16(v.w - __bfloat162float(h3));
        __nv_bfloat162 a, b;
        a.x = h0; a.y = h1; b.x = h2; b.y = h3;
        uint2 hp; hp.x = *(uint32_t*)&a; hp.y = *(uint32_t*)&b;
        a.x = l0; a.y = l1; b.x = l2; b.y = l3;
        uint2 lp; lp.x = *(uint32_t*)&a; lp.y = *(uint32_t*)&b;
        *(uint2*)(smem + SA_H + m * SROW + k * 2) = hp;
        *(uint2*)(smem + SA_L + m * SROW + k * 2) = lp;
    }
    asm volatile("cp.async.wait_group 0;" ::: "memory");
    __syncthreads();

    int mrow0 = (wid >> 2) * 32;         // 2 M-groups
    int ncol0 = (wid & 3) * 32;          // 4 N-groups
    float acc[2][4][4];
    #pragma unroll
    for (int mi = 0; mi < 2; mi++)
        #pragma unroll
        for (int ni = 0; ni < 4; ni++)
            #pragma unroll
            for (int q = 0; q < 4; q++) acc[mi][ni][q] = 0.f;

    // ldmatrix per-lane addresses.
    int l3 = lid & 7, grp = lid >> 3;
    uint32_t a_row = mrow0 + l3 + (grp & 1) * 8;
    uint32_t a_koff = (grp >> 1) * 16;
    uint32_t aH0 = sb + SA_H + a_row * SROW + a_koff;
    uint32_t aH1 = aH0 + 16 * SROW;
    uint32_t aL0 = aH0 + (SA_L - SA_H);
    uint32_t aL1 = aH1 + (SA_L - SA_H);
    uint32_t b_row = ncol0 + l3 + (grp >> 1) * 8;
    uint32_t b_koff = (grp & 1) * 16;
    uint32_t bH = sb + SB_H + b_row * SROW + b_koff;
    uint32_t bL = bH + (SB_L - SB_H);

    #pragma unroll
    for (int ks = 0; ks < 8; ks++) {
        uint32_t kb = ks * 32;
        uint32_t ah[2][4], al[2][4];
        ldsm4(ah[0], aH0 + kb);
        ldsm4(ah[1], aH1 + kb);
        ldsm4(al[0], aL0 + kb);
        ldsm4(al[1], aL1 + kb);
        #pragma unroll
        for (int p = 0; p < 2; p++) {        // ni pair (2p, 2p+1)
            uint32_t bh4[4], bl4[4];
            ldsm4(bh4, bH + p * 16 * SROW + kb);
            ldsm4(bl4, bL + p * 16 * SROW + kb);
            // pass-grouped: 4 independent accs per pass
            #pragma unroll
            for (int h = 0; h < 2; h++) {
                int ni = 2 * p + h;
                mma16816(acc[0][ni], ah[0], &bh4[2 * h]);
                mma16816(acc[1][ni], ah[1], &bh4[2 * h]);
            }
            #pragma unroll
            for (int h = 0; h < 2; h++) {
                int ni = 2 * p + h;
                mma16816(acc[0][ni], al[0], &bh4[2 * h]);
                mma16816(acc[1][ni], al[1], &bh4[2 * h]);
            }
            #pragma unroll
            for (int h = 0; h < 2; h++) {
                int ni = 2 * p + h;
                mma16816(acc[0][ni], ah[0], &bl4[2 * h]);
                mma16816(acc[1][ni], ah[1], &bl4[2 * h]);
            }
        }
    }

    // ---- epilogue: write y1 ----------------------------------------------------
    #pragma unroll
    for (int mi = 0; mi < 2; mi++) {
        int r0 = node0 + mrow0 + mi * 16 + gid;
        #pragma unroll
        for (int ni = 0; ni < 4; ni++) {
            int col = cbase + ncol0 + ni * 8 + tid4 * 2;
            if (r0 < n_nodes)
                *(float2*)(g_y1 + (size_t)r0 * NCOLS + col) =
                    make_float2(acc[mi][ni][0], acc[mi][ni][1]);
            if (r0 + 8 < n_nodes)
                *(float2*)(g_y1 + (size_t)(r0 + 8) * NCOLS + col) =
                    make_float2(acc[mi][ni][2], acc[mi][ni][3]);
        }
    }
}

// ------- K5: layer-1 edge scatter (deg scales folded); resets g_cnt ----------
__global__ void k_scatter1(const int* __restrict__ src, const int* __restrict__ dst,
                           int n_nodes, int n_edges) {
    if (blockIdx.x == 0 && threadIdx.x < NGMAX) g_cnt[threadIdx.x] = 0;
    int i = blockIdx.x * blockDim.x + threadIdx.x;
    int tot = NREL * n_edges * 8;
    if (i >= tot) return;
    int e = i >> 3, q = i & 7;
    int r = e / n_edges;
    int s = src[e], d = dst[e];
    float sc = g_rso[r * n_nodes + s] * g_rsi[r * n_nodes + d];
    float4 v = *(const float4*)(g_y1 + (size_t)s * NCOLS + r * HID + q * 4);
    v.x *= sc; v.y *= sc; v.z *= sc; v.w *= sc;
    atomicAdd((float4*)(g_h1 + (size_t)d * HID + q * 4), v);
}

// ---- K7: fused relu + layer-2 + mean-pool + classifier (edge -> out[64,2]) --
__global__ __launch_bounds__(256) void k_scatter2(const int* __restrict__ src,
                                                  const int* __restrict__ dst,
                                                  const int* __restrict__ gids,
                                                  const float* __restrict__ b1,
                                                  float* __restrict__ out,
                                                  int n_nodes, int n_edges) {
    __shared__ float zs[NGMAX * 2];
    __shared__ float Vs[NREL * HID * 2];
    __shared__ float inv_s[NGMAX];
    __shared__ float4 bias4[HID / 4];
    int t = threadIdx.x;
    if (t < NGMAX * 2) zs[t] = 0.f;
    for (int i = t; i < NREL * HID * 2; i += 256) Vs[i] = g_V[i];
    if (t < NGMAX) inv_s[t] = g_inv[t];
    if (t < HID) {
        float s = 0.f;
        #pragma unroll
        for (int r = 0; r < NREL; r++) s += b1[r * HID + t];
        ((float*)bias4)[t] = s;
    }
    __syncthreads();

    int te = NREL * n_edges;
    int e0 = blockIdx.x * EPB;
    #pragma unroll
    for (int it = 0; it < EPB / 256; it++) {
        int e = e0 + it * 256 + t;
        if (e < te) {
            int r = e / n_edges;
            int s = src[e], d = dst[e];
            int g = gids[d];
            float coeff = g_rso[r * n_nodes + s] * g_rsi[r * n_nodes + d] * inv_s[g];
            const float4* hp = (const float4*)(g_h1 + (size_t)s * HID);
            const float* vp = Vs + r * (HID * 2);
            float a0 = 0.f, a1 = 0.f;
            #pragma unroll
            for (int q = 0; q < 8; q++) {
                float4 hv = hp[q];
                float4 bq = bias4[q];
                hv.x = fmaxf(hv.x + bq.x, 0.f);
                hv.y = fmaxf(hv.y + bq.y, 0.f);
                hv.z = fmaxf(hv.z + bq.z, 0.f);
                hv.w = fmaxf(hv.w + bq.w, 0.f);
                a0 += hv.x * vp[q * 8 + 0] + hv.y * vp[q * 8 + 2] +
                      hv.z * vp[q * 8 + 4] + hv.w * vp[q * 8 + 6];
                a1 += hv.x * vp[q * 8 + 1] + hv.y * vp[q * 8 + 3] +
                      hv.z * vp[q * 8 + 5] + hv.w * vp[q * 8 + 7];
            }
            atomicAdd(&zs[g * 2 + 0], a0 * coeff);
            atomicAdd(&zs[g * 2 + 1], a1 * coeff);
        }
    }
    __syncthreads();
    if (t < NGMAX * 2) atomicAdd(&out[t], zs[t]);
}

// ---------------- launch ------------------------------------------------------
extern "C" void kernel_launch(void* const* d_in, const int* in_sizes, int n_in,
                              void* d_out, int out_size) {
    int off = (n_in >= 11) ? 1 : 0;
    const float* x   = (const float*)d_in[0];
    const int*   src = (const int*)d_in[1];
    const int*   dst = (const int*)d_in[2];
    const int*   gid = (const int*)d_in[3];
    const float* W1  = (const float*)d_in[4 + off];
    const float* b1  = (const float*)d_in[5 + off];
    const float* W2  = (const float*)d_in[6 + off];
    const float* b2  = (const float*)d_in[7 + off];
    const float* Wc  = (const float*)d_in[8 + off];
    const float* bc  = (const float*)d_in[9 + off];
    float* out = (float*)d_out;

    int n_nodes  = in_sizes[3];
    int n_edges  = in_sizes[1] / NREL;
    int n_graphs = out_size / 2;

    cudaFuncSetAttribute(k_gemm_mma, cudaFuncAttributeMaxDynamicSharedMemorySize,
                         SMEM_G);

    int tot1 = NREL * n_edges + n_nodes;
    k_deg<<<64 + (tot1 + 255) / 256, 256>>>(src, dst, gid, W1, n_nodes, n_edges);

    int tot2 = NREL * n_nodes + NREL * HID * 2 + 2 * n_graphs + (n_nodes * HID) / 4;
    k_prep<<<(tot2 + 255) / 256, 256>>>(W2, Wc, b2, bc, out, n_nodes, n_graphs);

    dim3 g4((n_nodes + 63) / 64, 2);
    k_gemm_mma<<<g4, 256, SMEM_G>>>(x, n_nodes);

    int tot5 = NREL * n_edges * 8;
    k_scatter1<<<(tot5 + 255) / 256, 256>>>(src, dst, n_nodes, n_edges);

    k_scatter2<<<(NREL * n_edges + EPB - 1) / EPB, 256>>>(src, dst, gid, b1, out,
                                                          n_nodes, n_edges);
}

// round 12
// speedup vs baseline: 1.2431x; 1.1800x over previous
#include <cuda_runtime.h>
#include <cuda_fp16.h>
#include <cstdint>

// ---------------- problem-size constants (fixed by this problem) -------------
#define MAXN   100000
#define NREL   8
#define INF    128
#define HID    32
#define NCOLS  (NREL*HID)      // 256
#define NGMAX  64
#define EPB    1024            // edges per block in scatter2

// ---------------- device scratch (static: no allocations allowed) ------------
// Replay-safety: h1 zeroed by k_prep at the START of every replay; deg arrays
// self-reset in k_prep; g_cnt resets in k_scatter1 block 0.
__device__ __align__(128) float g_y1[(size_t)MAXN * NCOLS];   // x @ [W1_0..W1_7]
__device__ __align__(128) float g_h1[(size_t)MAXN * HID];     // scatter1 accum
__device__ __align__(128) float g_dot[(size_t)MAXN * 16];     // relu(h1+b)·V_r, [n][r][2]
__device__ __align__(128) float g_rso[NREL * MAXN];           // rsqrt(max(deg_out,1))
__device__ __align__(128) float g_rsi[NREL * MAXN];           // rsqrt(max(deg_in,1))
__device__ __align__(128) int   g_dego[NREL * MAXN];          // reset by k_prep
__device__ __align__(128) int   g_degi[NREL * MAXN];          // reset by k_prep
__device__ __align__(128) int   g_cnt[NGMAX];                 // reset by k_scatter1
__device__ __align__(128) float g_inv[NGMAX];                 // 1/max(cnt,1)
__device__ __align__(128) float g_V[NREL * HID * 2];          // W2_r @ Wc
// fp16 weight image (hi only — 2-pass scheme needs no w_lo), [n][k], 256B/row
__device__ __align__(128) unsigned char g_wimg[65536];

__device__ __forceinline__ uint32_t smem_u32(const void* p) {
    uint32_t a;
    asm("{ .reg .u64 t; cvta.to.shared.u64 t, %1; cvt.u32.u64 %0, t; }" : "=r"(a) : "l"(p));
    return a;
}
__device__ __forceinline__ void cp16(uint32_t daddr, const void* src) {
    asm volatile("cp.async.cg.shared.global [%0], [%1], 16;" :: "r"(daddr), "l"(src));
}
__device__ __forceinline__ void ldsm4(uint32_t* r, uint32_t addr) {
    asm volatile("ldmatrix.sync.aligned.m8n8.x4.shared.b16 {%0,%1,%2,%3}, [%4];"
        : "=r"(r[0]), "=r"(r[1]), "=r"(r[2]), "=r"(r[3]) : "r"(addr));
}

// ---------------- K2: wconv (blocks 0-63) + degrees + graph counts ------------
__global__ void k_deg(const int* __restrict__ src, const int* __restrict__ dst,
                      const int* __restrict__ gids, const float* __restrict__ W1,
                      int n_nodes, int n_edges) {
    if (blockIdx.x < 64) {
        // W1 -> fp16 image, [n][k] layout (hi only)
        int i = blockIdx.x * blockDim.x + threadIdx.x;   // 0..16383
        int n = i >> 6, k = (i & 63) * 2;
        int r = n >> 5, f = n & 31;
        float w0 = W1[r * (INF * HID) + k * HID + f];
        float w1 = W1[r * (INF * HID) + (k + 1) * HID + f];
        __half2 hv;
        hv.x = __float2half(w0);
        hv.y = __float2half(w1);
        *(__half2*)(g_wimg + (uint32_t)n * 256u + (uint32_t)k * 2u) = hv;
        return;
    }
    int i = (blockIdx.x - 64) * blockDim.x + threadIdx.x;
    int te = NREL * n_edges;
    if (i < te) {
        int r = i / n_edges;
        atomicAdd(&g_dego[r * n_nodes + src[i]], 1);
        atomicAdd(&g_degi[r * n_nodes + dst[i]], 1);
    } else if (i < te + n_nodes) {
        atomicAdd(&g_cnt[gids[i - te]], 1);
    }
}

// ------ K3: rsqrt tables, V, out init, deg reset, h1 zero (replay start) -----
__global__ void k_prep(const float* __restrict__ W2, const float* __restrict__ Wc,
                       const float* __restrict__ b2, const float* __restrict__ bc,
                       float* __restrict__ out, int n_nodes, int n_graphs) {
    int i = blockIdx.x * blockDim.x + threadIdx.x;
    int t1 = NREL * n_nodes;
    int t2 = t1 + NREL * HID * 2;
    int t3 = t2 + 2 * n_graphs;
    if (i < t1) {
        g_rso[i] = rsqrtf((float)max(g_dego[i], 1));
        g_rsi[i] = rsqrtf((float)max(g_degi[i], 1));
        g_dego[i] = 0;                 // self-reset for next graph replay
        g_degi[i] = 0;
    } else if (i < t2) {
        int v = i - t1;
        int r = v >> 6, f = (v >> 1) & 31, o = v & 1;
        float s = 0.f;
        #pragma unroll
        for (int j = 0; j < HID; j++) s += W2[r * (HID * HID) + f * HID + j] * Wc[j * 2 + o];
        g_V[v] = s;
    } else if (i < t3) {
        int u = i - t2;
        int g = u >> 1, o = u & 1;
        if (o == 0) g_inv[g] = 1.f / (float)max(g_cnt[g], 1);
        float s = 0.f;
        for (int j = 0; j < HID; j++) {
            float bs = 0.f;
            #pragma unroll
            for (int r = 0; r < NREL; r++) bs += b2[r * HID + j];
            s += bs * Wc[j * 2 + o];
        }
        out[u] = bc[o] + (g_cnt[g] > 0 ? s : 0.f);   // empty graph -> pooled = 0
    } else if (i < t3 + (n_nodes * HID) / 4) {
        // zero h1 (float4) before scatter1 accumulates this replay
        ((float4*)g_h1)[i - t3] = make_float4(0.f, 0.f, 0.f, 0.f);
    }
}

// ---------------- K4: HMMA GEMM  y1 = x @ [W1_0..W1_7] ------------------------
// CTA: 64 nodes x 128 cols x full K=128. fp16 hi/lo 2-PASS scheme:
//   y = x_hi*w + x_lo*w   (w in fp16; dropped x_hi*w_lo term ~1.4e-4 rel RMS)
// 2/3 the MMAs of the 3-pass bf16 scheme (GEMM is at the HMMA issue floor —
// R8-R11 showed nothing else moves it). B_lo eliminated: smem 69.6KB, 2 CTA/SM.
// 256 threads, 8 warps (2M x 4N), warp tile 32x32.
#define SROW  272
#define SA_H  0
#define SA_L  (64 * SROW)                // 17408
#define SB_H  (2 * 64 * SROW)            // 34816
#define SMEM_G (SB_H + 128 * SROW)       // 69632

__device__ __forceinline__ void mma16816(float* c, const uint32_t* a, const uint32_t* b) {
    asm volatile("mma.sync.aligned.m16n8k16.row.col.f32.f16.f16.f32 "
        "{%0,%1,%2,%3}, {%4,%5,%6,%7}, {%8,%9}, {%0,%1,%2,%3};"
        : "+f"(c[0]), "+f"(c[1]), "+f"(c[2]), "+f"(c[3])
        : "r"(a[0]), "r"(a[1]), "r"(a[2]), "r"(a[3]), "r"(b[0]), "r"(b[1]));
}

__global__ __launch_bounds__(256, 2) void k_gemm_mma(const float* __restrict__ x,
                                                     int n_nodes) {
    extern __shared__ unsigned char smem[];
    uint32_t sb = smem_u32(smem);
    int t = threadIdx.x, wid = t >> 5, lid = t & 31;
    int gid = lid >> 2, tid4 = lid & 3;
    int node0 = blockIdx.x * 64;
    int cbase = blockIdx.y * 128;

    // ---- B: cp.async of this CTA's 128-col half of the fp16 image ------------
    {
        const unsigned char* bh = g_wimg;
        #pragma unroll
        for (int p = 0; p < 8; p++) {
            int idx = p * 256 + t;               // 0..2047
            int n = idx >> 4, c = idx & 15;      // n 0..127, c 0..15
            uint32_t so = (uint32_t)(cbase + n) * 256u + (uint32_t)c * 16u;
            cp16(sb + SB_H + n * SROW + c * 16, bh + so);
        }
        asm volatile("cp.async.commit_group;" ::: "memory");
    }
    // ---- A: load x, convert to fp16 hi/lo, store (overlaps B cp.async) -------
    #pragma unroll
    for (int p = 0; p < 8; p++) {
        int idx = p * 256 + t;                   // 0..2047
        int m = idx >> 5, k = (idx & 31) * 4;    // m 0..63
        int gn = node0 + m;
        float4 v = make_float4(0.f, 0.f, 0.f, 0.f);
        if (gn < n_nodes) v = *(const float4*)(x + (size_t)gn * INF + k);
        __half h0 = __float2half(v.x), h1 = __float2half(v.y);
        __half h2 = __float2half(v.z), h3 = __float2half(v.w);
        __half l0 = __float2half(v.x - __half2float(h0));
        __half l1 = __float2half(v.y - __half2float(h1));
        __half l2 = __float2half(v.z - __half2float(h2));
        __half l3 = __float2half(v.w - __half2float(h3));
        __half2 a, b;
        a.x = h0; a.y = h1; b.x = h2; b.y = h3;
        uint2 hp; hp.x = *(uint32_t*)&a; hp.y = *(uint32_t*)&b;
        a.x = l0; a.y = l1; b.x = l2; b.y = l3;
        uint2 lp; lp.x = *(uint32_t*)&a; lp.y = *(uint32_t*)&b;
        *(uint2*)(smem + SA_H + m * SROW + k * 2) = hp;
        *(uint2*)(smem + SA_L + m * SROW + k * 2) = lp;
    }
    asm volatile("cp.async.wait_group 0;" ::: "memory");
    __syncthreads();

    int mrow0 = (wid >> 2) * 32;         // 2 M-groups
    int ncol0 = (wid & 3) * 32;          // 4 N-groups
    float acc[2][4][4];
    #pragma unroll
    for (int mi = 0; mi < 2; mi++)
        #pragma unroll
        for (int ni = 0; ni < 4; ni++)
            #pragma unroll
            for (int q = 0; q < 4; q++) acc[mi][ni][q] = 0.f;

    // ldmatrix per-lane addresses.
    int l3 = lid & 7, grp = lid >> 3;
    uint32_t a_row = mrow0 + l3 + (grp & 1) * 8;
    uint32_t a_koff = (grp >> 1) * 16;
    uint32_t aH0 = sb + SA_H + a_row * SROW + a_koff;
    uint32_t aH1 = aH0 + 16 * SROW;
    uint32_t aL0 = aH0 + (SA_L - SA_H);
    uint32_t aL1 = aH1 + (SA_L - SA_H);
    uint32_t b_row = ncol0 + l3 + (grp >> 1) * 8;
    uint32_t b_koff = (grp & 1) * 16;
    uint32_t bH = sb + SB_H + b_row * SROW + b_koff;

    #pragma unroll
    for (int ks = 0; ks < 8; ks++) {
        uint32_t kb = ks * 32;
        uint32_t ah[2][4], al[2][4];
        ldsm4(ah[0], aH0 + kb);
        ldsm4(ah[1], aH1 + kb);
        ldsm4(al[0], aL0 + kb);
        ldsm4(al[1], aL1 + kb);
        #pragma unroll
        for (int p = 0; p < 2; p++) {        // ni pair (2p, 2p+1)
            uint32_t bh4[4];
            ldsm4(bh4, bH + p * 16 * SROW + kb);
            // pass 0: hi*w (4 independent accs)
            #pragma unroll
            for (int h = 0; h < 2; h++) {
                int ni = 2 * p + h;
                mma16816(acc[0][ni], ah[0], &bh4[2 * h]);
                mma16816(acc[1][ni], ah[1], &bh4[2 * h]);
            }
            // pass 1: lo*w
            #pragma unroll
            for (int h = 0; h < 2; h++) {
                int ni = 2 * p + h;
                mma16816(acc[0][ni], al[0], &bh4[2 * h]);
                mma16816(acc[1][ni], al[1], &bh4[2 * h]);
            }
        }
    }

    // ---- epilogue: write y1 ----------------------------------------------------
    #pragma unroll
    for (int mi = 0; mi < 2; mi++) {
        int r0 = node0 + mrow0 + mi * 16 + gid;
        #pragma unroll
        for (int ni = 0; ni < 4; ni++) {
            int col = cbase + ncol0 + ni * 8 + tid4 * 2;
            if (r0 < n_nodes)
                *(float2*)(g_y1 + (size_t)r0 * NCOLS + col) =
                    make_float2(acc[mi][ni][0], acc[mi][ni][1]);
            if (r0 + 8 < n_nodes)
                *(float2*)(g_y1 + (size_t)(r0 + 8) * NCOLS + col) =
                    make_float2(acc[mi][ni][2], acc[mi][ni][3]);
        }
    }
}

// ------- K5: layer-1 edge scatter (deg scales folded); resets g_cnt ----------
__global__ void k_scatter1(const int* __restrict__ src, const int* __restrict__ dst,
                           int n_nodes, int n_edges) {
    if (blockIdx.x == 0 && threadIdx.x < NGMAX) g_cnt[threadIdx.x] = 0;
    int i = blockIdx.x * blockDim.x + threadIdx.x;
    int tot = NREL * n_edges * 8;
    if (i >= tot) return;
    int e = i >> 3, q = i & 7;
    int r = e / n_edges;
    int s = src[e], d = dst[e];
    float sc = g_rso[r * n_nodes + s] * g_rsi[r * n_nodes + d];
    float4 v = *(const float4*)(g_y1 + (size_t)s * NCOLS + r * HID + q * 4);
    v.x *= sc; v.y *= sc; v.z *= sc; v.w *= sc;
    atomicAdd((float4*)(g_h1 + (size_t)d * HID + q * 4), v);
}

// ---- K6: per-node dot precompute: dot[n][r][:] = relu(h1[n]+bias) . V_r ------
__global__ __launch_bounds__(256) void k_dot(const float* __restrict__ b1,
                                             int n_nodes) {
    __shared__ float hs[32][33];        // 32 nodes x 32 feats, padded
    __shared__ float Vs[NREL * HID * 2];
    __shared__ float bias[HID];
    int t = threadIdx.x;
    for (int i = t; i < NREL * HID * 2; i += 256) Vs[i] = g_V[i];
    if (t < HID) {
        float s = 0.f;
        #pragma unroll
        for (int r = 0; r < NREL; r++) s += b1[r * HID + t];
        bias[t] = s;
    }
    __syncthreads();
    int node0 = blockIdx.x * 32;
    {
        int n = t >> 3, q = t & 7;       // node-local, feat quarter
        int gn = node0 + n;
        float4 v = make_float4(0.f, 0.f, 0.f, 0.f);
        if (gn < n_nodes) v = ((const float4*)(g_h1 + (size_t)gn * HID))[q];
        hs[n][q * 4 + 0] = fmaxf(v.x + bias[q * 4 + 0], 0.f);
        hs[n][q * 4 + 1] = fmaxf(v.y + bias[q * 4 + 1], 0.f);
        hs[n][q * 4 + 2] = fmaxf(v.z + bias[q * 4 + 2], 0.f);
        hs[n][q * 4 + 3] = fmaxf(v.w + bias[q * 4 + 3], 0.f);
    }
    __syncthreads();
    int n2 = t & 31, r2 = t >> 5;        // node-local, relation
    const float* vp = Vs + r2 * (HID * 2);
    float a0 = 0.f, a1 = 0.f;
    #pragma unroll
    for (int j = 0; j < HID; j++) {
        float h = hs[n2][j];
        a0 += h * vp[2 * j + 0];
        a1 += h * vp[2 * j + 1];
    }
    int gn2 = node0 + n2;
    if (gn2 < n_nodes)
        *(float2*)(g_dot + (size_t)gn2 * 16 + r2 * 2) = make_float2(a0, a1);
}

// ---- K7: layer-2 edge pass + mean-pool + classifier (8B gather per edge) ----
__global__ __launch_bounds__(256) void k_scatter2(const int* __restrict__ src,
                                                  const int* __restrict__ dst,
                                                  const int* __restrict__ gids,
                                                  float* __restrict__ out,
                                                  int n_nodes, int n_edges) {
    __shared__ float zs[NGMAX * 2];
    __shared__ float inv_s[NGMAX];
    int t = threadIdx.x;
    if (t < NGMAX * 2) zs[t] = 0.f;
    if (t < NGMAX) inv_s[t] = g_inv[t];
    __syncthreads();

    int te = NREL * n_edges;
    int e0 = blockIdx.x * EPB;
    #pragma unroll
    for (int it = 0; it < EPB / 256; it++) {
        int e = e0 + it * 256 + t;
        if (e < te) {
            int r = e / n_edges;
            int s = src[e], d = dst[e];
            int g = gids[d];
            float coeff = g_rso[r * n_nodes + s] * g_rsi[r * n_nodes + d] * inv_s[g];
            float2 dv = *(const float2*)(g_dot + (size_t)s * 16 + r * 2);
            atomicAdd(&zs[g * 2 + 0], dv.x * coeff);
            atomicAdd(&zs[g * 2 + 1], dv.y * coeff);
        }
    }
    __syncthreads();
    if (t < NGMAX * 2) atomicAdd(&out[t], zs[t]);
}

// ---------------- launch ------------------------------------------------------
extern "C" void kernel_launch(void* const* d_in, const int* in_sizes, int n_in,
                              void* d_out, int out_size) {
    int off = (n_in >= 11) ? 1 : 0;
    const float* x   = (const float*)d_in[0];
    const int*   src = (const int*)d_in[1];
    const int*   dst = (const int*)d_in[2];
    const int*   gid = (const int*)d_in[3];
    const float* W1  = (const float*)d_in[4 + off];
    const float* b1  = (const float*)d_in[5 + off];
    const float* W2  = (const float*)d_in[6 + off];
    const float* b2  = (const float*)d_in[7 + off];
    const float* Wc  = (const float*)d_in[8 + off];
    const float* bc  = (const float*)d_in[9 + off];
    float* out = (float*)d_out;

    int n_nodes  = in_sizes[3];
    int n_edges  = in_sizes[1] / NREL;
    int n_graphs = out_size / 2;

    cudaFuncSetAttribute(k_gemm_mma, cudaFuncAttributeMaxDynamicSharedMemorySize,
                         SMEM_G);

    int tot1 = NREL * n_edges + n_nodes;
    k_deg<<<64 + (tot1 + 255) / 256, 256>>>(src, dst, gid, W1, n_nodes, n_edges);

    int tot2 = NREL * n_nodes + NREL * HID * 2 + 2 * n_graphs + (n_nodes * HID) / 4;
    k_prep<<<(tot2 + 255) / 256, 256>>>(W2, Wc, b2, bc, out, n_nodes, n_graphs);

    dim3 g4((n_nodes + 63) / 64, 2);
    k_gemm_mma<<<g4, 256, SMEM_G>>>(x, n_nodes);

    int tot5 = NREL * n_edges * 8;
    k_scatter1<<<(tot5 + 255) / 256, 256>>>(src, dst, n_nodes, n_edges);

    k_dot<<<(n_nodes + 31) / 32, 256>>>(b1, n_nodes);

    k_scatter2<<<(NREL * n_edges + EPB - 1) / EPB, 256>>>(src, dst, gid, out,
                                                          n_nodes, n_edges);
}

// round 13
// speedup vs baseline: 1.2779x; 1.0280x over previous
#include <cuda_runtime.h>
#include <cuda_fp16.h>
#include <cstdint>

// ---------------- problem-size constants (fixed by this problem) -------------
#define MAXN   100000
#define NREL   8
#define INF    128
#define HID    32
#define NCOLS  (NREL*HID)      // 256
#define NGMAX  64
#define EPB    1024            // edges per block in scatter2

// ---------------- device scratch (static: no allocations allowed) ------------
// Replay-safety: h1 zeroed by k_prep at the START of every replay; deg arrays
// self-reset in k_prep; g_cnt resets in k_scatter1 block 0.
__device__ __align__(128) __half g_y1h[(size_t)MAXN * NCOLS]; // fp16 y1 * rso (51MB)
__device__ __align__(128) float g_h1[(size_t)MAXN * HID];     // scatter1 accum
__device__ __align__(128) float g_dot[(size_t)MAXN * 16];     // relu(h1+b)·V_r, [n][r][2]
__device__ __align__(128) float g_rso[NREL * MAXN];           // rsqrt(max(deg_out,1))
__device__ __align__(128) float g_rsi[NREL * MAXN];           // rsqrt(max(deg_in,1))
__device__ __align__(128) int   g_dego[NREL * MAXN];          // reset by k_prep
__device__ __align__(128) int   g_degi[NREL * MAXN];          // reset by k_prep
__device__ __align__(128) int   g_cnt[NGMAX];                 // reset by k_scatter1
__device__ __align__(128) float g_inv[NGMAX];                 // 1/max(cnt,1)
__device__ __align__(128) float g_V[NREL * HID * 2];          // W2_r @ Wc
// fp16 weight image, [n][k] layout, 256B/row
__device__ __align__(128) unsigned char g_wimg[65536];

__device__ __forceinline__ uint32_t smem_u32(const void* p) {
    uint32_t a;
    asm("{ .reg .u64 t; cvta.to.shared.u64 t, %1; cvt.u32.u64 %0, t; }" : "=r"(a) : "l"(p));
    return a;
}
__device__ __forceinline__ void cp16(uint32_t daddr, const void* src) {
    asm volatile("cp.async.cg.shared.global [%0], [%1], 16;" :: "r"(daddr), "l"(src));
}
__device__ __forceinline__ void ldsm4(uint32_t* r, uint32_t addr) {
    asm volatile("ldmatrix.sync.aligned.m8n8.x4.shared.b16 {%0,%1,%2,%3}, [%4];"
        : "=r"(r[0]), "=r"(r[1]), "=r"(r[2]), "=r"(r[3]) : "r"(addr));
}

// ---------------- K2: wconv (blocks 0-63) + degrees + graph counts ------------
__global__ void k_deg(const int* __restrict__ src, const int* __restrict__ dst,
                      const int* __restrict__ gids, const float* __restrict__ W1,
                      int n_nodes, int n_edges) {
    if (blockIdx.x < 64) {
        int i = blockIdx.x * blockDim.x + threadIdx.x;   // 0..16383
        int n = i >> 6, k = (i & 63) * 2;
        int r = n >> 5, f = n & 31;
        float w0 = W1[r * (INF * HID) + k * HID + f];
        float w1 = W1[r * (INF * HID) + (k + 1) * HID + f];
        __half2 hv;
        hv.x = __float2half(w0);
        hv.y = __float2half(w1);
        *(__half2*)(g_wimg + (uint32_t)n * 256u + (uint32_t)k * 2u) = hv;
        return;
    }
    int i = (blockIdx.x - 64) * blockDim.x + threadIdx.x;
    int te = NREL * n_edges;
    if (i < te) {
        int r = i / n_edges;
        atomicAdd(&g_dego[r * n_nodes + src[i]], 1);
        atomicAdd(&g_degi[r * n_nodes + dst[i]], 1);
    } else if (i < te + n_nodes) {
        atomicAdd(&g_cnt[gids[i - te]], 1);
    }
}

// ------ K3: rsqrt tables, V, out init, deg reset, h1 zero (replay start) -----
__global__ void k_prep(const float* __restrict__ W2, const float* __restrict__ Wc,
                       const float* __restrict__ b2, const float* __restrict__ bc,
                       float* __restrict__ out, int n_nodes, int n_graphs) {
    int i = blockIdx.x * blockDim.x + threadIdx.x;
    int t1 = NREL * n_nodes;
    int t2 = t1 + NREL * HID * 2;
    int t3 = t2 + 2 * n_graphs;
    if (i < t1) {
        g_rso[i] = rsqrtf((float)max(g_dego[i], 1));
        g_rsi[i] = rsqrtf((float)max(g_degi[i], 1));
        g_dego[i] = 0;                 // self-reset for next graph replay
        g_degi[i] = 0;
    } else if (i < t2) {
        int v = i - t1;
        int r = v >> 6, f = (v >> 1) & 31, o = v & 1;
        float s = 0.f;
        #pragma unroll
        for (int j = 0; j < HID; j++) s += W2[r * (HID * HID) + f * HID + j] * Wc[j * 2 + o];
        g_V[v] = s;
    } else if (i < t3) {
        int u = i - t2;
        int g = u >> 1, o = u & 1;
        if (o == 0) g_inv[g] = 1.f / (float)max(g_cnt[g], 1);
        float s = 0.f;
        for (int j = 0; j < HID; j++) {
            float bs = 0.f;
            #pragma unroll
            for (int r = 0; r < NREL; r++) bs += b2[r * HID + j];
            s += bs * Wc[j * 2 + o];
        }
        out[u] = bc[o] + (g_cnt[g] > 0 ? s : 0.f);   // empty graph -> pooled = 0
    } else if (i < t3 + (n_nodes * HID) / 4) {
        ((float4*)g_h1)[i - t3] = make_float4(0.f, 0.f, 0.f, 0.f);
    }
}

// ---------------- K4: HMMA GEMM  y1h = (x @ W1) * rso, fp16 -------------------
// CTA: 64 nodes x 128 cols x full K=128. fp16 hi/lo 2-pass scheme.
// smem 69.6KB -> 3 CTAs/SM (204KB). Epilogue folds rso (relation fixed per
// warp) and stores fp16: y1 traffic halved on both write and gather sides.
#define SROW  272
#define SA_H  0
#define SA_L  (64 * SROW)                // 17408
#define SB_H  (2 * 64 * SROW)            // 34816
#define SMEM_G (SB_H + 128 * SROW)       // 69632

__device__ __forceinline__ void mma16816(float* c, const uint32_t* a, const uint32_t* b) {
    asm volatile("mma.sync.aligned.m16n8k16.row.col.f32.f16.f16.f32 "
        "{%0,%1,%2,%3}, {%4,%5,%6,%7}, {%8,%9}, {%0,%1,%2,%3};"
        : "+f"(c[0]), "+f"(c[1]), "+f"(c[2]), "+f"(c[3])
        : "r"(a[0]), "r"(a[1]), "r"(a[2]), "r"(a[3]), "r"(b[0]), "r"(b[1]));
}

__global__ __launch_bounds__(256, 3) void k_gemm_mma(const float* __restrict__ x,
                                                     int n_nodes) {
    extern __shared__ unsigned char smem[];
    uint32_t sb = smem_u32(smem);
    int t = threadIdx.x, wid = t >> 5, lid = t & 31;
    int gid = lid >> 2, tid4 = lid & 3;
    int node0 = blockIdx.x * 64;
    int cbase = blockIdx.y * 128;

    // ---- B: cp.async of this CTA's 128-col half of the fp16 image ------------
    {
        const unsigned char* bh = g_wimg;
        #pragma unroll
        for (int p = 0; p < 8; p++) {
            int idx = p * 256 + t;               // 0..2047
            int n = idx >> 4, c = idx & 15;
            uint32_t so = (uint32_t)(cbase + n) * 256u + (uint32_t)c * 16u;
            cp16(sb + SB_H + n * SROW + c * 16, bh + so);
        }
        asm volatile("cp.async.commit_group;" ::: "memory");
    }
    // ---- A: load x, convert to fp16 hi/lo, store (overlaps B cp.async) -------
    #pragma unroll
    for (int p = 0; p < 8; p++) {
        int idx = p * 256 + t;                   // 0..2047
        int m = idx >> 5, k = (idx & 31) * 4;
        int gn = node0 + m;
        float4 v = make_float4(0.f, 0.f, 0.f, 0.f);
        if (gn < n_nodes) v = *(const float4*)(x + (size_t)gn * INF + k);
        __half h0 = __float2half(v.x), h1 = __float2half(v.y);
        __half h2 = __float2half(v.z), h3 = __float2half(v.w);
        __half l0 = __float2half(v.x - __half2float(h0));
        __half l1 = __float2half(v.y - __half2float(h1));
        __half l2 = __float2half(v.z - __half2float(h2));
        __half l3 = __float2half(v.w - __half2float(h3));
        __half2 a, b;
        a.x = h0; a.y = h1; b.x = h2; b.y = h3;
        uint2 hp; hp.x = *(uint32_t*)&a; hp.y = *(uint32_t*)&b;
        a.x = l0; a.y = l1; b.x = l2; b.y = l3;
        uint2 lp; lp.x = *(uint32_t*)&a; lp.y = *(uint32_t*)&b;
        *(uint2*)(smem + SA_H + m * SROW + k * 2) = hp;
        *(uint2*)(smem + SA_L + m * SROW + k * 2) = lp;
    }
    asm volatile("cp.async.wait_group 0;" ::: "memory");
    __syncthreads();

    int mrow0 = (wid >> 2) * 32;         // 2 M-groups
    int ncol0 = (wid & 3) * 32;          // 4 N-groups
    float acc[2][4][4];
    #pragma unroll
    for (int mi = 0; mi < 2; mi++)
        #pragma unroll
        for (int ni = 0; ni < 4; ni++)
            #pragma unroll
            for (int q = 0; q < 4; q++) acc[mi][ni][q] = 0.f;

    int l3 = lid & 7, grp = lid >> 3;
    uint32_t a_row = mrow0 + l3 + (grp & 1) * 8;
    uint32_t a_koff = (grp >> 1) * 16;
    uint32_t aH0 = sb + SA_H + a_row * SROW + a_koff;
    uint32_t aH1 = aH0 + 16 * SROW;
    uint32_t aL0 = aH0 + (SA_L - SA_H);
    uint32_t aL1 = aH1 + (SA_L - SA_H);
    uint32_t b_row = ncol0 + l3 + (grp >> 1) * 8;
    uint32_t b_koff = (grp & 1) * 16;
    uint32_t bH = sb + SB_H + b_row * SROW + b_koff;

    #pragma unroll
    for (int ks = 0; ks < 8; ks++) {
        uint32_t kb = ks * 32;
        uint32_t ah[2][4], al[2][4];
        ldsm4(ah[0], aH0 + kb);
        ldsm4(ah[1], aH1 + kb);
        ldsm4(al[0], aL0 + kb);
        ldsm4(al[1], aL1 + kb);
        #pragma unroll
        for (int p = 0; p < 2; p++) {
            uint32_t bh4[4];
            ldsm4(bh4, bH + p * 16 * SROW + kb);
            #pragma unroll
            for (int h = 0; h < 2; h++) {
                int ni = 2 * p + h;
                mma16816(acc[0][ni], ah[0], &bh4[2 * h]);
                mma16816(acc[1][ni], ah[1], &bh4[2 * h]);
            }
            #pragma unroll
            for (int h = 0; h < 2; h++) {
                int ni = 2 * p + h;
                mma16816(acc[0][ni], al[0], &bh4[2 * h]);
                mma16816(acc[1][ni], al[1], &bh4[2 * h]);
            }
        }
    }

    // ---- epilogue: scale by rso (relation fixed per warp) and store fp16 -----
    int rel = (cbase + ncol0) >> 5;      // relation of this warp's 32 cols
    #pragma unroll
    for (int mi = 0; mi < 2; mi++) {
        int r0 = node0 + mrow0 + mi * 16 + gid;
        float sc0 = (r0 < n_nodes) ? g_rso[rel * n_nodes + r0] : 0.f;
        float sc1 = (r0 + 8 < n_nodes) ? g_rso[rel * n_nodes + r0 + 8] : 0.f;
        #pragma unroll
        for (int ni = 0; ni < 4; ni++) {
            int col = cbase + ncol0 + ni * 8 + tid4 * 2;
            if (r0 < n_nodes) {
                __half2 v; v.x = __float2half(acc[mi][ni][0] * sc0);
                           v.y = __float2half(acc[mi][ni][1] * sc0);
                *(__half2*)(g_y1h + (size_t)r0 * NCOLS + col) = v;
            }
            if (r0 + 8 < n_nodes) {
                __half2 v; v.x = __float2half(acc[mi][ni][2] * sc1);
                           v.y = __float2half(acc[mi][ni][3] * sc1);
                *(__half2*)(g_y1h + (size_t)(r0 + 8) * NCOLS + col) = v;
            }
        }
    }
}

// ------- K5: layer-1 edge scatter (rso folded into y1h); resets g_cnt --------
__global__ void k_scatter1(const int* __restrict__ src, const int* __restrict__ dst,
                           int n_nodes, int n_edges) {
    if (blockIdx.x == 0 && threadIdx.x < NGMAX) g_cnt[threadIdx.x] = 0;
    int i = blockIdx.x * blockDim.x + threadIdx.x;
    int tot = NREL * n_edges * 8;
    if (i >= tot) return;
    int e = i >> 3, q = i & 7;
    int r = e / n_edges;
    int s = src[e], d = dst[e];
    float sc = g_rsi[r * n_nodes + d];
    uint2 raw = *(const uint2*)(g_y1h + (size_t)s * NCOLS + r * HID + q * 4);
    __half2 h01 = *(__half2*)&raw.x;
    __half2 h23 = *(__half2*)&raw.y;
    float2 f01 = __half22float2(h01);
    float2 f23 = __half22float2(h23);
    float4 v = make_float4(f01.x * sc, f01.y * sc, f23.x * sc, f23.y * sc);
    atomicAdd((float4*)(g_h1 + (size_t)d * HID + q * 4), v);
}

// ---- K6: per-node dot precompute: dot[n][r][:] = relu(h1[n]+bias) . V_r ------
__global__ __launch_bounds__(256) void k_dot(const float* __restrict__ b1,
                                             int n_nodes) {
    __shared__ float hs[32][33];
    __shared__ float Vs[NREL * HID * 2];
    __shared__ float bias[HID];
    int t = threadIdx.x;
    for (int i = t; i < NREL * HID * 2; i += 256) Vs[i] = g_V[i];
    if (t < HID) {
        float s = 0.f;
        #pragma unroll
        for (int r = 0; r < NREL; r++) s += b1[r * HID + t];
        bias[t] = s;
    }
    __syncthreads();
    int node0 = blockIdx.x * 32;
    {
        int n = t >> 3, q = t & 7;
        int gn = node0 + n;
        float4 v = make_float4(0.f, 0.f, 0.f, 0.f);
        if (gn < n_nodes) v = ((const float4*)(g_h1 + (size_t)gn * HID))[q];
        hs[n][q * 4 + 0] = fmaxf(v.x + bias[q * 4 + 0], 0.f);
        hs[n][q * 4 + 1] = fmaxf(v.y + bias[q * 4 + 1], 0.f);
        hs[n][q * 4 + 2] = fmaxf(v.z + bias[q * 4 + 2], 0.f);
        hs[n][q * 4 + 3] = fmaxf(v.w + bias[q * 4 + 3], 0.f);
    }
    __syncthreads();
    int n2 = t & 31, r2 = t >> 5;
    const float* vp = Vs + r2 * (HID * 2);
    float a0 = 0.f, a1 = 0.f;
    #pragma unroll
    for (int j = 0; j < HID; j++) {
        float h = hs[n2][j];
        a0 += h * vp[2 * j + 0];
        a1 += h * vp[2 * j + 1];
    }
    int gn2 = node0 + n2;
    if (gn2 < n_nodes)
        *(float2*)(g_dot + (size_t)gn2 * 16 + r2 * 2) = make_float2(a0, a1);
}

// ---- K7: layer-2 edge pass + mean-pool + classifier (8B gather per edge) ----
__global__ __launch_bounds__(256) void k_scatter2(const int* __restrict__ src,
                                                  const int* __restrict__ dst,
                                                  const int* __restrict__ gids,
                                                  float* __restrict__ out,
                                                  int n_nodes, int n_edges) {
    __shared__ float zs[NGMAX * 2];
    __shared__ float inv_s[NGMAX];
    int t = threadIdx.x;
    if (t < NGMAX * 2) zs[t] = 0.f;
    if (t < NGMAX) inv_s[t] = g_inv[t];
    __syncthreads();

    int te = NREL * n_edges;
    int e0 = blockIdx.x * EPB;
    #pragma unroll
    for (int it = 0; it < EPB / 256; it++) {
        int e = e0 + it * 256 + t;
        if (e < te) {
            int r = e / n_edges;
            int s = src[e], d = dst[e];
            int g = gids[d];
            float coeff = g_rso[r * n_nodes + s] * g_rsi[r * n_nodes + d] * inv_s[g];
            float2 dv = *(const float2*)(g_dot + (size_t)s * 16 + r * 2);
            atomicAdd(&zs[g * 2 + 0], dv.x * coeff);
            atomicAdd(&zs[g * 2 + 1], dv.y * coeff);
        }
    }
    __syncthreads();
    if (t < NGMAX * 2) atomicAdd(&out[t], zs[t]);
}

// ---------------- launch ------------------------------------------------------
extern "C" void kernel_launch(void* const* d_in, const int* in_sizes, int n_in,
                              void* d_out, int out_size) {
    int off = (n_in >= 11) ? 1 : 0;
    const float* x   = (const float*)d_in[0];
    const int*   src = (const int*)d_in[1];
    const int*   dst = (const int*)d_in[2];
    const int*   gid = (const int*)d_in[3];
    const float* W1  = (const float*)d_in[4 + off];
    const float* b1  = (const float*)d_in[5 + off];
    const float* W2  = (const float*)d_in[6 + off];
    const float* b2  = (const float*)d_in[7 + off];
    const float* Wc  = (const float*)d_in[8 + off];
    const float* bc  = (const float*)d_in[9 + off];
    float* out = (float*)d_out;

    int n_nodes  = in_sizes[3];
    int n_edges  = in_sizes[1] / NREL;
    int n_graphs = out_size / 2;

    cudaFuncSetAttribute(k_gemm_mma, cudaFuncAttributeMaxDynamicSharedMemorySize,
                         SMEM_G);

    int tot1 = NREL * n_edges + n_nodes;
    k_deg<<<64 + (tot1 + 255) / 256, 256>>>(src, dst, gid, W1, n_nodes, n_edges);

    int tot2 = NREL * n_nodes + NREL * HID * 2 + 2 * n_graphs + (n_nodes * HID) / 4;
    k_prep<<<(tot2 + 255) / 256, 256>>>(W2, Wc, b2, bc, out, n_nodes, n_graphs);

    dim3 g4((n_nodes + 63) / 64, 2);
    k_gemm_mma<<<g4, 256, SMEM_G>>>(x, n_nodes);

    int tot5 = NREL * n_edges * 8;
    k_scatter1<<<(tot5 + 255) / 256, 256>>>(src, dst, n_nodes, n_edges);

    k_dot<<<(n_nodes + 31) / 32, 256>>>(b1, n_nodes);

    k_scatter2<<<(NREL * n_edges + EPB - 1) / EPB, 256>>>(src, dst, gid, out,
                                                          n_nodes, n_edges);
}

// round 14
// speedup vs baseline: 1.3537x; 1.0593x over previous
#include <cuda_runtime.h>
#include <cuda_fp16.h>
#include <cstdint>

// ---------------- problem-size constants (fixed by this problem) -------------
#define MAXN   100000
#define NREL   8
#define INF    128
#define HID    32
#define NCOLS  (NREL*HID)      // 256
#define NGMAX  64
#define EPB    1024            // edges per block in scatter2

// ---------------- device scratch (static: no allocations allowed) ------------
// Replay-safety: h1 zeroed by k_prep at the START of every replay; deg arrays
// self-reset in k_prep; g_cnt resets in k_scatter1 block 0.
__device__ __align__(128) __half g_y1h[(size_t)MAXN * NCOLS]; // fp16 y1 * rso (51MB)
__device__ __align__(128) float g_h1[(size_t)MAXN * HID];     // scatter1 accum
__device__ __align__(128) float g_dot[(size_t)MAXN * 16];     // relu(h1+b)·V_r, [n][r][2]
__device__ __align__(128) float g_rso[NREL * MAXN];           // rsqrt(max(deg_out,1))
__device__ __align__(128) float g_rsi[NREL * MAXN];           // rsqrt(max(deg_in,1))
__device__ __align__(128) int   g_dego[NREL * MAXN];          // reset by k_prep
__device__ __align__(128) int   g_degi[NREL * MAXN];          // reset by k_prep
__device__ __align__(128) int   g_cnt[NGMAX];                 // reset by k_scatter1
__device__ __align__(128) float g_inv[NGMAX];                 // 1/max(cnt,1)
__device__ __align__(128) float g_V[NREL * HID * 2];          // W2_r @ Wc
// fp16 weight image, [n][k] layout, 256B/row
__device__ __align__(128) unsigned char g_wimg[65536];

__device__ __forceinline__ uint32_t smem_u32(const void* p) {
    uint32_t a;
    asm("{ .reg .u64 t; cvta.to.shared.u64 t, %1; cvt.u32.u64 %0, t; }" : "=r"(a) : "l"(p));
    return a;
}
__device__ __forceinline__ void cp16(uint32_t daddr, const void* src) {
    asm volatile("cp.async.cg.shared.global [%0], [%1], 16;" :: "r"(daddr), "l"(src));
}
__device__ __forceinline__ void ldsm4(uint32_t* r, uint32_t addr) {
    asm volatile("ldmatrix.sync.aligned.m8n8.x4.shared.b16 {%0,%1,%2,%3}, [%4];"
        : "=r"(r[0]), "=r"(r[1]), "=r"(r[2]), "=r"(r[3]) : "r"(addr));
}

// ---------------- K2: wconv (blocks 0-63) + degrees + graph counts ------------
__global__ void k_deg(const int* __restrict__ src, const int* __restrict__ dst,
                      const int* __restrict__ gids, const float* __restrict__ W1,
                      int n_nodes, int n_edges) {
    if (blockIdx.x < 64) {
        int i = blockIdx.x * blockDim.x + threadIdx.x;   // 0..16383
        int n = i >> 6, k = (i & 63) * 2;
        int r = n >> 5, f = n & 31;
        float w0 = W1[r * (INF * HID) + k * HID + f];
        float w1 = W1[r * (INF * HID) + (k + 1) * HID + f];
        __half2 hv;
        hv.x = __float2half(w0);
        hv.y = __float2half(w1);
        *(__half2*)(g_wimg + (uint32_t)n * 256u + (uint32_t)k * 2u) = hv;
        return;
    }
    int i = (blockIdx.x - 64) * blockDim.x + threadIdx.x;
    int te = NREL * n_edges;
    if (i < te) {
        int r = i / n_edges;
        atomicAdd(&g_dego[r * n_nodes + src[i]], 1);
        atomicAdd(&g_degi[r * n_nodes + dst[i]], 1);
    } else if (i < te + n_nodes) {
        atomicAdd(&g_cnt[gids[i - te]], 1);
    }
}

// ------ K3: rsqrt tables, V, out init, deg reset, h1 zero (replay start) -----
__global__ void k_prep(const float* __restrict__ W2, const float* __restrict__ Wc,
                       const float* __restrict__ b2, const float* __restrict__ bc,
                       float* __restrict__ out, int n_nodes, int n_graphs) {
    int i = blockIdx.x * blockDim.x + threadIdx.x;
    int t1 = NREL * n_nodes;
    int t2 = t1 + NREL * HID * 2;
    int t3 = t2 + 2 * n_graphs;
    if (i < t1) {
        g_rso[i] = rsqrtf((float)max(g_dego[i], 1));
        g_rsi[i] = rsqrtf((float)max(g_degi[i], 1));
        g_dego[i] = 0;                 // self-reset for next graph replay
        g_degi[i] = 0;
    } else if (i < t2) {
        int v = i - t1;
        int r = v >> 6, f = (v >> 1) & 31, o = v & 1;
        float s = 0.f;
        #pragma unroll
        for (int j = 0; j < HID; j++) s += W2[r * (HID * HID) + f * HID + j] * Wc[j * 2 + o];
        g_V[v] = s;
    } else if (i < t3) {
        int u = i - t2;
        int g = u >> 1, o = u & 1;
        if (o == 0) g_inv[g] = 1.f / (float)max(g_cnt[g], 1);
        float s = 0.f;
        for (int j = 0; j < HID; j++) {
            float bs = 0.f;
            #pragma unroll
            for (int r = 0; r < NREL; r++) bs += b2[r * HID + j];
            s += bs * Wc[j * 2 + o];
        }
        out[u] = bc[o] + (g_cnt[g] > 0 ? s : 0.f);   // empty graph -> pooled = 0
    } else if (i < t3 + (n_nodes * HID) / 4) {
        ((float4*)g_h1)[i - t3] = make_float4(0.f, 0.f, 0.f, 0.f);
    }
}

// ---------------- K4: HMMA GEMM  y1h = (x @ W1) * rso, fp16 -------------------
// CTA: 64 nodes x 128 cols x full K=128. SINGLE-PASS pure fp16 (x and w both
// rounded to fp16): empirically the pooling averages per-element rounding to
// ~1e-5 at the output per source (R12/R13), so one more 2.4e-4 RMS source is
// safe. Half the MMAs of R13. smem 51KB -> 3 CTAs/SM.
#define SROW  272
#define SA_H  0
#define SB_H  (64 * SROW)                // 17408
#define SMEM_G (SB_H + 128 * SROW)       // 52224

__device__ __forceinline__ void mma16816(float* c, const uint32_t* a, const uint32_t* b) {
    asm volatile("mma.sync.aligned.m16n8k16.row.col.f32.f16.f16.f32 "
        "{%0,%1,%2,%3}, {%4,%5,%6,%7}, {%8,%9}, {%0,%1,%2,%3};"
        : "+f"(c[0]), "+f"(c[1]), "+f"(c[2]), "+f"(c[3])
        : "r"(a[0]), "r"(a[1]), "r"(a[2]), "r"(a[3]), "r"(b[0]), "r"(b[1]));
}

__global__ __launch_bounds__(256, 3) void k_gemm_mma(const float* __restrict__ x,
                                                     int n_nodes) {
    extern __shared__ unsigned char smem[];
    uint32_t sb = smem_u32(smem);
    int t = threadIdx.x, wid = t >> 5, lid = t & 31;
    int gid = lid >> 2, tid4 = lid & 3;
    int node0 = blockIdx.x * 64;
    int cbase = blockIdx.y * 128;

    // ---- B: cp.async of this CTA's 128-col half of the fp16 image ------------
    {
        const unsigned char* bh = g_wimg;
        #pragma unroll
        for (int p = 0; p < 8; p++) {
            int idx = p * 256 + t;               // 0..2047
            int n = idx >> 4, c = idx & 15;
            uint32_t so = (uint32_t)(cbase + n) * 256u + (uint32_t)c * 16u;
            cp16(sb + SB_H + n * SROW + c * 16, bh + so);
        }
        asm volatile("cp.async.commit_group;" ::: "memory");
    }
    // ---- A: load x, convert to fp16, store (overlaps B cp.async) -------------
    #pragma unroll
    for (int p = 0; p < 8; p++) {
        int idx = p * 256 + t;                   // 0..2047
        int m = idx >> 5, k = (idx & 31) * 4;
        int gn = node0 + m;
        float4 v = make_float4(0.f, 0.f, 0.f, 0.f);
        if (gn < n_nodes) v = *(const float4*)(x + (size_t)gn * INF + k);
        __half2 a, b;
        a.x = __float2half(v.x); a.y = __float2half(v.y);
        b.x = __float2half(v.z); b.y = __float2half(v.w);
        uint2 hp; hp.x = *(uint32_t*)&a; hp.y = *(uint32_t*)&b;
        *(uint2*)(smem + SA_H + m * SROW + k * 2) = hp;
    }
    asm volatile("cp.async.wait_group 0;" ::: "memory");
    __syncthreads();

    int mrow0 = (wid >> 2) * 32;         // 2 M-groups
    int ncol0 = (wid & 3) * 32;          // 4 N-groups
    float acc[2][4][4];
    #pragma unroll
    for (int mi = 0; mi < 2; mi++)
        #pragma unroll
        for (int ni = 0; ni < 4; ni++)
            #pragma unroll
            for (int q = 0; q < 4; q++) acc[mi][ni][q] = 0.f;

    int l3 = lid & 7, grp = lid >> 3;
    uint32_t a_row = mrow0 + l3 + (grp & 1) * 8;
    uint32_t a_koff = (grp >> 1) * 16;
    uint32_t aH0 = sb + SA_H + a_row * SROW + a_koff;
    uint32_t aH1 = aH0 + 16 * SROW;
    uint32_t b_row = ncol0 + l3 + (grp >> 1) * 8;
    uint32_t b_koff = (grp & 1) * 16;
    uint32_t bH = sb + SB_H + b_row * SROW + b_koff;

    #pragma unroll
    for (int ks = 0; ks < 8; ks++) {
        uint32_t kb = ks * 32;
        uint32_t ah[2][4];
        ldsm4(ah[0], aH0 + kb);
        ldsm4(ah[1], aH1 + kb);
        #pragma unroll
        for (int p = 0; p < 2; p++) {
            uint32_t bh4[4];
            ldsm4(bh4, bH + p * 16 * SROW + kb);
            #pragma unroll
            for (int h = 0; h < 2; h++) {
                int ni = 2 * p + h;
                mma16816(acc[0][ni], ah[0], &bh4[2 * h]);
                mma16816(acc[1][ni], ah[1], &bh4[2 * h]);
            }
        }
    }

    // ---- epilogue: scale by rso (relation fixed per warp) and store fp16 -----
    int rel = (cbase + ncol0) >> 5;      // relation of this warp's 32 cols
    #pragma unroll
    for (int mi = 0; mi < 2; mi++) {
        int r0 = node0 + mrow0 + mi * 16 + gid;
        float sc0 = (r0 < n_nodes) ? g_rso[rel * n_nodes + r0] : 0.f;
        float sc1 = (r0 + 8 < n_nodes) ? g_rso[rel * n_nodes + r0 + 8] : 0.f;
        #pragma unroll
        for (int ni = 0; ni < 4; ni++) {
            int col = cbase + ncol0 + ni * 8 + tid4 * 2;
            if (r0 < n_nodes) {
                __half2 v; v.x = __float2half(acc[mi][ni][0] * sc0);
                           v.y = __float2half(acc[mi][ni][1] * sc0);
                *(__half2*)(g_y1h + (size_t)r0 * NCOLS + col) = v;
            }
            if (r0 + 8 < n_nodes) {
                __half2 v; v.x = __float2half(acc[mi][ni][2] * sc1);
                           v.y = __float2half(acc[mi][ni][3] * sc1);
                *(__half2*)(g_y1h + (size_t)(r0 + 8) * NCOLS + col) = v;
            }
        }
    }
}

// ------- K5: layer-1 edge scatter (rso folded into y1h); resets g_cnt --------
__global__ void k_scatter1(const int* __restrict__ src, const int* __restrict__ dst,
                           int n_nodes, int n_edges) {
    if (blockIdx.x == 0 && threadIdx.x < NGMAX) g_cnt[threadIdx.x] = 0;
    int i = blockIdx.x * blockDim.x + threadIdx.x;
    int tot = NREL * n_edges * 8;
    if (i >= tot) return;
    int e = i >> 3, q = i & 7;
    int r = e / n_edges;
    int s = src[e], d = dst[e];
    float sc = g_rsi[r * n_nodes + d];
    uint2 raw = *(const uint2*)(g_y1h + (size_t)s * NCOLS + r * HID + q * 4);
    __half2 h01 = *(__half2*)&raw.x;
    __half2 h23 = *(__half2*)&raw.y;
    float2 f01 = __half22float2(h01);
    float2 f23 = __half22float2(h23);
    float4 v = make_float4(f01.x * sc, f01.y * sc, f23.x * sc, f23.y * sc);
    atomicAdd((float4*)(g_h1 + (size_t)d * HID + q * 4), v);
}

// ---- K6: per-node dot precompute: dot[n][r][:] = relu(h1[n]+bias) . V_r ------
__global__ __launch_bounds__(256) void k_dot(const float* __restrict__ b1,
                                             int n_nodes) {
    __shared__ float hs[32][33];
    __shared__ float Vs[NREL * HID * 2];
    __shared__ float bias[HID];
    int t = threadIdx.x;
    for (int i = t; i < NREL * HID * 2; i += 256) Vs[i] = g_V[i];
    if (t < HID) {
        float s = 0.f;
        #pragma unroll
        for (int r = 0; r < NREL; r++) s += b1[r * HID + t];
        bias[t] = s;
    }
    __syncthreads();
    int node0 = blockIdx.x * 32;
    {
        int n = t >> 3, q = t & 7;
        int gn = node0 + n;
        float4 v = make_float4(0.f, 0.f, 0.f, 0.f);
        if (gn < n_nodes) v = ((const float4*)(g_h1 + (size_t)gn * HID))[q];
        hs[n][q * 4 + 0] = fmaxf(v.x + bias[q * 4 + 0], 0.f);
        hs[n][q * 4 + 1] = fmaxf(v.y + bias[q * 4 + 1], 0.f);
        hs[n][q * 4 + 2] = fmaxf(v.z + bias[q * 4 + 2], 0.f);
        hs[n][q * 4 + 3] = fmaxf(v.w + bias[q * 4 + 3], 0.f);
    }
    __syncthreads();
    int n2 = t & 31, r2 = t >> 5;
    const float* vp = Vs + r2 * (HID * 2);
    float a0 = 0.f, a1 = 0.f;
    #pragma unroll
    for (int j = 0; j < HID; j++) {
        float h = hs[n2][j];
        a0 += h * vp[2 * j + 0];
        a1 += h * vp[2 * j + 1];
    }
    int gn2 = node0 + n2;
    if (gn2 < n_nodes)
        *(float2*)(g_dot + (size_t)gn2 * 16 + r2 * 2) = make_float2(a0, a1);
}

// ---- K7: layer-2 edge pass + mean-pool + classifier (8B gather per edge) ----
__global__ __launch_bounds__(256) void k_scatter2(const int* __restrict__ src,
                                                  const int* __restrict__ dst,
                                                  const int* __restrict__ gids,
                                                  float* __restrict__ out,
                                                  int n_nodes, int n_edges) {
    __shared__ float zs[NGMAX * 2];
    __shared__ float inv_s[NGMAX];
    int t = threadIdx.x;
    if (t < NGMAX * 2) zs[t] = 0.f;
    if (t < NGMAX) inv_s[t] = g_inv[t];
    __syncthreads();

    int te = NREL * n_edges;
    int e0 = blockIdx.x * EPB;
    #pragma unroll
    for (int it = 0; it < EPB / 256; it++) {
        int e = e0 + it * 256 + t;
        if (e < te) {
            int r = e / n_edges;
            int s = src[e], d = dst[e];
            int g = gids[d];
            float coeff = g_rso[r * n_nodes + s] * g_rsi[r * n_nodes + d] * inv_s[g];
            float2 dv = *(const float2*)(g_dot + (size_t)s * 16 + r * 2);
            atomicAdd(&zs[g * 2 + 0], dv.x * coeff);
            atomicAdd(&zs[g * 2 + 1], dv.y * coeff);
        }
    }
    __syncthreads();
    if (t < NGMAX * 2) atomicAdd(&out[t], zs[t]);
}

// ---------------- launch ------------------------------------------------------
extern "C" void kernel_launch(void* const* d_in, const int* in_sizes, int n_in,
                              void* d_out, int out_size) {
    int off = (n_in >= 11) ? 1 : 0;
    const float* x   = (const float*)d_in[0];
    const int*   src = (const int*)d_in[1];
    const int*   dst = (const int*)d_in[2];
    const int*   gid = (const int*)d_in[3];
    const float* W1  = (const float*)d_in[4 + off];
    const float* b1  = (const float*)d_in[5 + off];
    const float* W2  = (const float*)d_in[6 + off];
    const float* b2  = (const float*)d_in[7 + off];
    const float* Wc  = (const float*)d_in[8 + off];
    const float* bc  = (const float*)d_in[9 + off];
    float* out = (float*)d_out;

    int n_nodes  = in_sizes[3];
    int n_edges  = in_sizes[1] / NREL;
    int n_graphs = out_size / 2;

    cudaFuncSetAttribute(k_gemm_mma, cudaFuncAttributeMaxDynamicSharedMemorySize,
                         SMEM_G);

    int tot1 = NREL * n_edges + n_nodes;
    k_deg<<<64 + (tot1 + 255) / 256, 256>>>(src, dst, gid, W1, n_nodes, n_edges);

    int tot2 = NREL * n_nodes + NREL * HID * 2 + 2 * n_graphs + (n_nodes * HID) / 4;
    k_prep<<<(tot2 + 255) / 256, 256>>>(W2, Wc, b2, bc, out, n_nodes, n_graphs);

    dim3 g4((n_nodes + 63) / 64, 2);
    k_gemm_mma<<<g4, 256, SMEM_G>>>(x, n_nodes);

    int tot5 = NREL * n_edges * 8;
    k_scatter1<<<(tot5 + 255) / 256, 256>>>(src, dst, n_nodes, n_edges);

    k_dot<<<(n_nodes + 31) / 32, 256>>>(b1, n_nodes);

    k_scatter2<<<(NREL * n_edges + EPB - 1) / EPB, 256>>>(src, dst, gid, out,
                                                          n_nodes, n_edges);
}

// round 15
// speedup vs baseline: 1.3928x; 1.0288x over previous
#include <cuda_runtime.h>
#include <cuda_fp16.h>
#include <cstdint>

// ---------------- problem-size constants (fixed by this problem) -------------
#define MAXN   100000
#define NREL   8
#define INF    128
#define HID    32
#define NCOLS  (NREL*HID)      // 256
#define NGMAX  64
#define EPB    1024            // edges per block in scatter2

// ---------------- device scratch (static: no allocations allowed) ------------
// Replay-safety: h1 zeroed by k_prep at the START of every replay; deg arrays
// self-reset in k_prep; g_cnt resets in k_scatter1 block 0.
__device__ __align__(128) __half g_y1h[(size_t)MAXN * NCOLS]; // fp16 y1 * rso (51MB)
__device__ __align__(128) float g_h1[(size_t)MAXN * HID];     // scatter1 accum
__device__ __align__(128) float g_dot[(size_t)MAXN * 16];     // relu(h1+b)·V_r, [n][r][2]
__device__ __align__(128) float g_rso[NREL * MAXN];           // rsqrt(max(deg_out,1))
__device__ __align__(128) float g_rsi[NREL * MAXN];           // rsqrt(max(deg_in,1))
__device__ __align__(128) int   g_dego[NREL * MAXN];          // reset by k_prep
__device__ __align__(128) int   g_degi[NREL * MAXN];          // reset by k_prep
__device__ __align__(128) int   g_cnt[NGMAX];                 // reset by k_scatter1
__device__ __align__(128) float g_inv[NGMAX];                 // 1/max(cnt,1)
__device__ __align__(128) float g_V[NREL * HID * 2];          // W2_r @ Wc
// fp16 weight image, [n][k] layout, 256B/row
__device__ __align__(128) unsigned char g_wimg[65536];

__device__ __forceinline__ uint32_t smem_u32(const void* p) {
    uint32_t a;
    asm("{ .reg .u64 t; cvta.to.shared.u64 t, %1; cvt.u32.u64 %0, t; }" : "=r"(a) : "l"(p));
    return a;
}
__device__ __forceinline__ void cp16(uint32_t daddr, const void* src) {
    asm volatile("cp.async.cg.shared.global [%0], [%1], 16;" :: "r"(daddr), "l"(src));
}
__device__ __forceinline__ void ldsm4(uint32_t* r, uint32_t addr) {
    asm volatile("ldmatrix.sync.aligned.m8n8.x4.shared.b16 {%0,%1,%2,%3}, [%4];"
        : "=r"(r[0]), "=r"(r[1]), "=r"(r[2]), "=r"(r[3]) : "r"(addr));
}

// ---------------- K2: wconv (blocks 0-63) + degrees + graph counts ------------
__global__ void k_deg(const int* __restrict__ src, const int* __restrict__ dst,
                      const int* __restrict__ gids, const float* __restrict__ W1,
                      int n_nodes, int n_edges) {
    if (blockIdx.x < 64) {
        int i = blockIdx.x * blockDim.x + threadIdx.x;   // 0..16383
        int n = i >> 6, k = (i & 63) * 2;
        int r = n >> 5, f = n & 31;
        float w0 = W1[r * (INF * HID) + k * HID + f];
        float w1 = W1[r * (INF * HID) + (k + 1) * HID + f];
        __half2 hv;
        hv.x = __float2half(w0);
        hv.y = __float2half(w1);
        *(__half2*)(g_wimg + (uint32_t)n * 256u + (uint32_t)k * 2u) = hv;
        return;
    }
    int i = (blockIdx.x - 64) * blockDim.x + threadIdx.x;
    int te = NREL * n_edges;
    if (i < te) {
        int r = i / n_edges;
        atomicAdd(&g_dego[r * n_nodes + src[i]], 1);
        atomicAdd(&g_degi[r * n_nodes + dst[i]], 1);
    } else if (i < te + n_nodes) {
        atomicAdd(&g_cnt[gids[i - te]], 1);
    }
}

// ------ K3: rsqrt tables, V, out init, deg reset, h1 zero (replay start) -----
__global__ void k_prep(const float* __restrict__ W2, const float* __restrict__ Wc,
                       const float* __restrict__ b2, const float* __restrict__ bc,
                       float* __restrict__ out, int n_nodes, int n_graphs) {
    int i = blockIdx.x * blockDim.x + threadIdx.x;
    int t1 = NREL * n_nodes;
    int t2 = t1 + NREL * HID * 2;
    int t3 = t2 + 2 * n_graphs;
    if (i < t1) {
        g_rso[i] = rsqrtf((float)max(g_dego[i], 1));
        g_rsi[i] = rsqrtf((float)max(g_degi[i], 1));
        g_dego[i] = 0;                 // self-reset for next graph replay
        g_degi[i] = 0;
    } else if (i < t2) {
        int v = i - t1;
        int r = v >> 6, f = (v >> 1) & 31, o = v & 1;
        float s = 0.f;
        #pragma unroll
        for (int j = 0; j < HID; j++) s += W2[r * (HID * HID) + f * HID + j] * Wc[j * 2 + o];
        g_V[v] = s;
    } else if (i < t3) {
        int u = i - t2;
        int g = u >> 1, o = u & 1;
        if (o == 0) g_inv[g] = 1.f / (float)max(g_cnt[g], 1);
        float s = 0.f;
        for (int j = 0; j < HID; j++) {
            float bs = 0.f;
            #pragma unroll
            for (int r = 0; r < NREL; r++) bs += b2[r * HID + j];
            s += bs * Wc[j * 2 + o];
        }
        out[u] = bc[o] + (g_cnt[g] > 0 ? s : 0.f);   // empty graph -> pooled = 0
    } else if (i < t3 + (n_nodes * HID) / 4) {
        ((float4*)g_h1)[i - t3] = make_float4(0.f, 0.f, 0.f, 0.f);
    }
}

// ---------------- K4: HMMA GEMM  y1h = (x @ W1) * rso, fp16 -------------------
// CTA: 64 nodes x ALL 256 cols x full K=128 -> x read ONCE (was twice with
// grid.y=2; GEMM is DRAM-bound after R14 halved the MMAs). Single-pass fp16.
// smem 87KB -> 2 CTAs/SM. 8 warps (2M x 4N), warp tile 32x64, acc 64 regs.
#define SROW  272
#define SA_H  0
#define SB_H  (64 * SROW)                // 17408
#define SMEM_G (SB_H + 256 * SROW)       // 87040

__device__ __forceinline__ void mma16816(float* c, const uint32_t* a, const uint32_t* b) {
    asm volatile("mma.sync.aligned.m16n8k16.row.col.f32.f16.f16.f32 "
        "{%0,%1,%2,%3}, {%4,%5,%6,%7}, {%8,%9}, {%0,%1,%2,%3};"
        : "+f"(c[0]), "+f"(c[1]), "+f"(c[2]), "+f"(c[3])
        : "r"(a[0]), "r"(a[1]), "r"(a[2]), "r"(a[3]), "r"(b[0]), "r"(b[1]));
}

__global__ __launch_bounds__(256, 2) void k_gemm_mma(const float* __restrict__ x,
                                                     int n_nodes) {
    extern __shared__ unsigned char smem[];
    uint32_t sb = smem_u32(smem);
    int t = threadIdx.x, wid = t >> 5, lid = t & 31;
    int gid = lid >> 2, tid4 = lid & 3;
    int node0 = blockIdx.x * 64;

    // ---- B: cp.async of the FULL fp16 weight image (256 rows) ----------------
    {
        const unsigned char* bh = g_wimg;
        #pragma unroll
        for (int p = 0; p < 16; p++) {
            int idx = p * 256 + t;               // 0..4095
            int n = idx >> 4, c = idx & 15;      // n 0..255, c 0..15
            uint32_t so = (uint32_t)n * 256u + (uint32_t)c * 16u;
            cp16(sb + SB_H + n * SROW + c * 16, bh + so);
        }
        asm volatile("cp.async.commit_group;" ::: "memory");
    }
    // ---- A: load x, convert to fp16, store (overlaps B cp.async) -------------
    #pragma unroll
    for (int p = 0; p < 8; p++) {
        int idx = p * 256 + t;                   // 0..2047
        int m = idx >> 5, k = (idx & 31) * 4;    // m 0..63
        int gn = node0 + m;
        float4 v = make_float4(0.f, 0.f, 0.f, 0.f);
        if (gn < n_nodes) v = *(const float4*)(x + (size_t)gn * INF + k);
        __half2 a, b;
        a.x = __float2half(v.x); a.y = __float2half(v.y);
        b.x = __float2half(v.z); b.y = __float2half(v.w);
        uint2 hp; hp.x = *(uint32_t*)&a; hp.y = *(uint32_t*)&b;
        *(uint2*)(smem + SA_H + m * SROW + k * 2) = hp;
    }
    asm volatile("cp.async.wait_group 0;" ::: "memory");
    __syncthreads();

    int mrow0 = (wid >> 2) * 32;         // 2 M-groups
    int ncol0 = (wid & 3) * 64;          // 4 N-groups of 64 cols (2 relations)
    float acc[2][8][4];
    #pragma unroll
    for (int mi = 0; mi < 2; mi++)
        #pragma unroll
        for (int ni = 0; ni < 8; ni++)
            #pragma unroll
            for (int q = 0; q < 4; q++) acc[mi][ni][q] = 0.f;

    int l3 = lid & 7, grp = lid >> 3;
    uint32_t a_row = mrow0 + l3 + (grp & 1) * 8;
    uint32_t a_koff = (grp >> 1) * 16;
    uint32_t aH0 = sb + SA_H + a_row * SROW + a_koff;
    uint32_t aH1 = aH0 + 16 * SROW;
    uint32_t b_row = ncol0 + l3 + (grp >> 1) * 8;
    uint32_t b_koff = (grp & 1) * 16;
    uint32_t bH = sb + SB_H + b_row * SROW + b_koff;

    #pragma unroll
    for (int ks = 0; ks < 8; ks++) {
        uint32_t kb = ks * 32;
        uint32_t ah[2][4];
        ldsm4(ah[0], aH0 + kb);
        ldsm4(ah[1], aH1 + kb);
        #pragma unroll
        for (int p = 0; p < 4; p++) {        // ni pair (2p, 2p+1)
            uint32_t bh4[4];
            ldsm4(bh4, bH + p * 16 * SROW + kb);
            #pragma unroll
            for (int h = 0; h < 2; h++) {
                int ni = 2 * p + h;
                mma16816(acc[0][ni], ah[0], &bh4[2 * h]);
                mma16816(acc[1][ni], ah[1], &bh4[2 * h]);
            }
        }
    }

    // ---- epilogue: scale by rso (2 relations per warp) and store fp16 --------
    int relbase = ncol0 >> 5;            // relations relbase, relbase+1
    #pragma unroll
    for (int mi = 0; mi < 2; mi++) {
        int r0 = node0 + mrow0 + mi * 16 + gid;
        float sc0[2] = {0.f, 0.f}, sc1[2] = {0.f, 0.f};
        if (r0 < n_nodes) {
            sc0[0] = g_rso[relbase * n_nodes + r0];
            sc0[1] = g_rso[(relbase + 1) * n_nodes + r0];
        }
        if (r0 + 8 < n_nodes) {
            sc1[0] = g_rso[relbase * n_nodes + r0 + 8];
            sc1[1] = g_rso[(relbase + 1) * n_nodes + r0 + 8];
        }
        #pragma unroll
        for (int ni = 0; ni < 8; ni++) {
            int col = ncol0 + ni * 8 + tid4 * 2;
            int rh = ni >> 2;
            if (r0 < n_nodes) {
                __half2 v; v.x = __float2half(acc[mi][ni][0] * sc0[rh]);
                           v.y = __float2half(acc[mi][ni][1] * sc0[rh]);
                *(__half2*)(g_y1h + (size_t)r0 * NCOLS + col) = v;
            }
            if (r0 + 8 < n_nodes) {
                __half2 v; v.x = __float2half(acc[mi][ni][2] * sc1[rh]);
                           v.y = __float2half(acc[mi][ni][3] * sc1[rh]);
                *(__half2*)(g_y1h + (size_t)(r0 + 8) * NCOLS + col) = v;
            }
        }
    }
}

// ------- K5: layer-1 edge scatter (rso folded into y1h); resets g_cnt --------
__global__ void k_scatter1(const int* __restrict__ src, const int* __restrict__ dst,
                           int n_nodes, int n_edges) {
    if (blockIdx.x == 0 && threadIdx.x < NGMAX) g_cnt[threadIdx.x] = 0;
    int i = blockIdx.x * blockDim.x + threadIdx.x;
    int tot = NREL * n_edges * 8;
    if (i >= tot) return;
    int e = i >> 3, q = i & 7;
    int r = e / n_edges;
    int s = src[e], d = dst[e];
    float sc = g_rsi[r * n_nodes + d];
    uint2 raw = *(const uint2*)(g_y1h + (size_t)s * NCOLS + r * HID + q * 4);
    __half2 h01 = *(__half2*)&raw.x;
    __half2 h23 = *(__half2*)&raw.y;
    float2 f01 = __half22float2(h01);
    float2 f23 = __half22float2(h23);
    float4 v = make_float4(f01.x * sc, f01.y * sc, f23.x * sc, f23.y * sc);
    atomicAdd((float4*)(g_h1 + (size_t)d * HID + q * 4), v);
}

// ---- K6: per-node dot precompute: dot[n][r][:] = relu(h1[n]+bias) . V_r ------
__global__ __launch_bounds__(256) void k_dot(const float* __restrict__ b1,
                                             int n_nodes) {
    __shared__ float hs[32][33];
    __shared__ float Vs[NREL * HID * 2];
    __shared__ float bias[HID];
    int t = threadIdx.x;
    for (int i = t; i < NREL * HID * 2; i += 256) Vs[i] = g_V[i];
    if (t < HID) {
        float s = 0.f;
        #pragma unroll
        for (int r = 0; r < NREL; r++) s += b1[r * HID + t];
        bias[t] = s;
    }
    __syncthreads();
    int node0 = blockIdx.x * 32;
    {
        int n = t >> 3, q = t & 7;
        int gn = node0 + n;
        float4 v = make_float4(0.f, 0.f, 0.f, 0.f);
        if (gn < n_nodes) v = ((const float4*)(g_h1 + (size_t)gn * HID))[q];
        hs[n][q * 4 + 0] = fmaxf(v.x + bias[q * 4 + 0], 0.f);
        hs[n][q * 4 + 1] = fmaxf(v.y + bias[q * 4 + 1], 0.f);
        hs[n][q * 4 + 2] = fmaxf(v.z + bias[q * 4 + 2], 0.f);
        hs[n][q * 4 + 3] = fmaxf(v.w + bias[q * 4 + 3], 0.f);
    }
    __syncthreads();
    int n2 = t & 31, r2 = t >> 5;
    const float* vp = Vs + r2 * (HID * 2);
    float a0 = 0.f, a1 = 0.f;
    #pragma unroll
    for (int j = 0; j < HID; j++) {
        float h = hs[n2][j];
        a0 += h * vp[2 * j + 0];
        a1 += h * vp[2 * j + 1];
    }
    int gn2 = node0 + n2;
    if (gn2 < n_nodes)
        *(float2*)(g_dot + (size_t)gn2 * 16 + r2 * 2) = make_float2(a0, a1);
}

// ---- K7: layer-2 edge pass + mean-pool + classifier (8B gather per edge) ----
__global__ __launch_bounds__(256) void k_scatter2(const int* __restrict__ src,
                                                  const int* __restrict__ dst,
                                                  const int* __restrict__ gids,
                                                  float* __restrict__ out,
                                                  int n_nodes, int n_edges) {
    __shared__ float zs[NGMAX * 2];
    __shared__ float inv_s[NGMAX];
    int t = threadIdx.x;
    if (t < NGMAX * 2) zs[t] = 0.f;
    if (t < NGMAX) inv_s[t] = g_inv[t];
    __syncthreads();

    int te = NREL * n_edges;
    int e0 = blockIdx.x * EPB;
    #pragma unroll
    for (int it = 0; it < EPB / 256; it++) {
        int e = e0 + it * 256 + t;
        if (e < te) {
            int r = e / n_edges;
            int s = src[e], d = dst[e];
            int g = gids[d];
            float coeff = g_rso[r * n_nodes + s] * g_rsi[r * n_nodes + d] * inv_s[g];
            float2 dv = *(const float2*)(g_dot + (size_t)s * 16 + r * 2);
            atomicAdd(&zs[g * 2 + 0], dv.x * coeff);
            atomicAdd(&zs[g * 2 + 1], dv.y * coeff);
        }
    }
    __syncthreads();
    if (t < NGMAX * 2) atomicAdd(&out[t], zs[t]);
}

// ---------------- launch ------------------------------------------------------
extern "C" void kernel_launch(void* const* d_in, const int* in_sizes, int n_in,
                              void* d_out, int out_size) {
    int off = (n_in >= 11) ? 1 : 0;
    const float* x   = (const float*)d_in[0];
    const int*   src = (const int*)d_in[1];
    const int*   dst = (const int*)d_in[2];
    const int*   gid = (const int*)d_in[3];
    const float* W1  = (const float*)d_in[4 + off];
    const float* b1  = (const float*)d_in[5 + off];
    const float* W2  = (const float*)d_in[6 + off];
    const float* b2  = (const float*)d_in[7 + off];
    const float* Wc  = (const float*)d_in[8 + off];
    const float* bc  = (const float*)d_in[9 + off];
    float* out = (float*)d_out;

    int n_nodes  = in_sizes[3];
    int n_edges  = in_sizes[1] / NREL;
    int n_graphs = out_size / 2;

    cudaFuncSetAttribute(k_gemm_mma, cudaFuncAttributeMaxDynamicSharedMemorySize,
                         SMEM_G);

    int tot1 = NREL * n_edges + n_nodes;
    k_deg<<<64 + (tot1 + 255) / 256, 256>>>(src, dst, gid, W1, n_nodes, n_edges);

    int tot2 = NREL * n_nodes + NREL * HID * 2 + 2 * n_graphs + (n_nodes * HID) / 4;
    k_prep<<<(tot2 + 255) / 256, 256>>>(W2, Wc, b2, bc, out, n_nodes, n_graphs);

    k_gemm_mma<<<(n_nodes + 63) / 64, 256, SMEM_G>>>(x, n_nodes);

    int tot5 = NREL * n_edges * 8;
    k_scatter1<<<(tot5 + 255) / 256, 256>>>(src, dst, n_nodes, n_edges);

    k_dot<<<(n_nodes + 31) / 32, 256>>>(b1, n_nodes);

    k_scatter2<<<(NREL * n_edges + EPB - 1) / EPB, 256>>>(src, dst, gid, out,
                                                          n_nodes, n_edges);
}